// round 1
// baseline (speedup 1.0000x reference)
#include <cuda_runtime.h>
#include <stdint.h>

// Problem constants
#define CDIM 512
#define GDIM 1024
#define PDIM 128
#define MROWS (PDIM * GDIM)      // 131072
#define NUM_IDS 64
#define EPS_BN 1e-5f

// Scratch (device globals; no cudaMalloc allowed)
__device__ float g_h1[(size_t)MROWS * CDIM];   // 256 MB intermediate h1
__device__ float g_u[MROWS * 2];               // u = t @ Wc  (partial sums via atomics)
__device__ float g_U[PDIM * NUM_IDS * 2];      // per-(p, class) sums of u
__device__ int   g_cnt[NUM_IDS];               // class counts of y_g

// ---------------------------------------------------------------------------
// Zero the small scratch buffers (g_u must be 0 before GEMM2's atomics)
// ---------------------------------------------------------------------------
__global__ void zero_scratch_kernel() {
    int i = blockIdx.x * blockDim.x + threadIdx.x;
    if (i < MROWS * 2) g_u[i] = 0.0f;
    if (i < PDIM * NUM_IDS * 2) g_U[i] = 0.0f;
    if (i < NUM_IDS) g_cnt[i] = 0;
}

// ---------------------------------------------------------------------------
// Tiled fp32 GEMM: [M,512] @ [512,512], BM=BN=128, BK=16, 256 thr, 8x8/thread
// MODE 0: A = d (param), out = lrelu(bn1(acc+b)) -> g_h1
// MODE 1: A = g_h1,      t = lrelu(bn2(acc+b)); u += t @ Wc (atomics into g_u)
// ---------------------------------------------------------------------------
template <int MODE>
__global__ __launch_bounds__(256, 2)
void gemm512_kernel(const float* __restrict__ Ain,
                    const float* __restrict__ B,
                    const float* __restrict__ bias,
                    const float* __restrict__ gam,
                    const float* __restrict__ bet,
                    const float* __restrict__ rm,
                    const float* __restrict__ rv,
                    const float* __restrict__ Wc)
{
    constexpr int BM = 128, BN = 128, BK = 16;
    __shared__ float sA[BK][BM];
    __shared__ float sB[BK][BN];

    const float* __restrict__ A = (MODE == 0) ? Ain : g_h1;

    const int tid = threadIdx.x;
    const int bm = blockIdx.y * BM;
    const int bn = blockIdx.x * BN;
    const int tm = (tid >> 4) * 8;   // 16 row-groups of 8
    const int tn = (tid & 15) * 8;   // 16 col-groups of 8

    float acc[8][8] = {};

    for (int k0 = 0; k0 < CDIM; k0 += BK) {
        // Load A tile (128x16) transposed into sA[k][m]
#pragma unroll
        for (int it = 0; it < 2; it++) {
            int idx = tid + it * 256;          // 0..511 float4 slots
            int row = idx >> 2;                // 4 float4 per row (BK=16)
            int c4  = (idx & 3) * 4;
            float4 v = *reinterpret_cast<const float4*>(
                &A[(size_t)(bm + row) * CDIM + k0 + c4]);
            sA[c4 + 0][row] = v.x;
            sA[c4 + 1][row] = v.y;
            sA[c4 + 2][row] = v.z;
            sA[c4 + 3][row] = v.w;
        }
        // Load B tile (16x128) direct
#pragma unroll
        for (int it = 0; it < 2; it++) {
            int idx = tid + it * 256;
            int row = idx >> 5;                // 32 float4 per row (BN=128)
            int c4  = (idx & 31) * 4;
            *reinterpret_cast<float4*>(&sB[row][c4]) =
                *reinterpret_cast<const float4*>(
                    &B[(size_t)(k0 + row) * CDIM + bn + c4]);
        }
        __syncthreads();

#pragma unroll
        for (int k = 0; k < BK; k++) {
            float ra[8], rb[8];
#pragma unroll
            for (int i = 0; i < 8; i++) ra[i] = sA[k][tm + i];
#pragma unroll
            for (int j = 0; j < 8; j++) rb[j] = sB[k][tn + j];
#pragma unroll
            for (int i = 0; i < 8; i++)
#pragma unroll
                for (int j = 0; j < 8; j++)
                    acc[i][j] = fmaf(ra[i], rb[j], acc[i][j]);
        }
        __syncthreads();
    }

    // BN epilogue coefficients: t = lrelu(acc * sc + of)
    float sc[8], of[8];
#pragma unroll
    for (int j = 0; j < 8; j++) {
        int col = bn + tn + j;
        float inv = rsqrtf(rv[col] + EPS_BN) * gam[col];
        sc[j] = inv;
        of[j] = (bias[col] - rm[col]) * inv + bet[col];
    }

    if (MODE == 0) {
#pragma unroll
        for (int i = 0; i < 8; i++) {
            float o[8];
#pragma unroll
            for (int j = 0; j < 8; j++) {
                float v = fmaf(acc[i][j], sc[j], of[j]);
                o[j] = (v >= 0.0f) ? v : 0.1f * v;
            }
            size_t row = (size_t)(bm + tm + i);
            *reinterpret_cast<float4*>(&g_h1[row * CDIM + bn + tn]) =
                make_float4(o[0], o[1], o[2], o[3]);
            *reinterpret_cast<float4*>(&g_h1[row * CDIM + bn + tn + 4]) =
                make_float4(o[4], o[5], o[6], o[7]);
        }
    } else {
        // Fold t into u = t @ Wc  (2 output columns), block-reduce then global atomics
        float wc0[8], wc1[8];
#pragma unroll
        for (int j = 0; j < 8; j++) {
            int col = bn + tn + j;
            wc0[j] = Wc[col * 2 + 0];
            wc1[j] = Wc[col * 2 + 1];
        }
        __shared__ float red[BM][2];
        if (tid < BM) { red[tid][0] = 0.0f; red[tid][1] = 0.0f; }
        __syncthreads();
#pragma unroll
        for (int i = 0; i < 8; i++) {
            float p0 = 0.0f, p1 = 0.0f;
#pragma unroll
            for (int j = 0; j < 8; j++) {
                float v = fmaf(acc[i][j], sc[j], of[j]);
                v = (v >= 0.0f) ? v : 0.1f * v;
                p0 = fmaf(v, wc0[j], p0);
                p1 = fmaf(v, wc1[j], p1);
            }
            atomicAdd(&red[tm + i][0], p0);
            atomicAdd(&red[tm + i][1], p1);
        }
        __syncthreads();
        if (tid < BM) {
            atomicAdd(&g_u[(size_t)(bm + tid) * 2 + 0], red[tid][0]);
            atomicAdd(&g_u[(size_t)(bm + tid) * 2 + 1], red[tid][1]);
        }
    }
}

// ---------------------------------------------------------------------------
// Per-(p, class) sums of u; block per p. Block 0 also records class counts.
// ---------------------------------------------------------------------------
__global__ void class_sums_kernel(const int* __restrict__ y_g) {
    int p = blockIdx.x;
    __shared__ float bins[NUM_IDS][2];
    __shared__ int cbin[NUM_IDS];
    int tid = threadIdx.x;
    if (tid < NUM_IDS) { bins[tid][0] = 0.0f; bins[tid][1] = 0.0f; cbin[tid] = 0; }
    __syncthreads();
    for (int g = tid; g < GDIM; g += blockDim.x) {
        int k = y_g[g];
        size_t base = (size_t)(p * GDIM + g) * 2;
        atomicAdd(&bins[k][0], g_u[base + 0]);
        atomicAdd(&bins[k][1], g_u[base + 1]);
        if (p == 0) atomicAdd(&cbin[k], 1);
    }
    __syncthreads();
    if (tid < NUM_IDS) {
        g_U[(p * NUM_IDS + tid) * 2 + 0] = bins[tid][0];
        g_U[(p * NUM_IDS + tid) * 2 + 1] = bins[tid][1];
        if (p == 0) g_cnt[tid] = cbin[tid];
    }
}

// ---------------------------------------------------------------------------
// Final assembly: result[p,h,:] = (U[p,class(h),:] + u[p,h,:])/(n_k+1) + bc
// plus label[p,h] = (y_p[p] == y_g[h]) in the layout selected by `mode`.
// ---------------------------------------------------------------------------
__global__ void finalize_kernel(const int* __restrict__ y_p,
                                const int* __restrict__ y_g,
                                const float* __restrict__ bc,
                                float* __restrict__ out, int mode)
{
    int idx = blockIdx.x * blockDim.x + threadIdx.x;
    if (idx >= MROWS) return;
    int p = idx >> 10;      // / GDIM
    int h = idx & 1023;
    int k = y_g[h];
    float inv = 1.0f / (float)(g_cnt[k] + 1);
    size_t ub = (size_t)idx * 2;
    float r0 = (g_U[(p * NUM_IDS + k) * 2 + 0] + g_u[ub + 0]) * inv + bc[0];
    float r1 = (g_U[(p * NUM_IDS + k) * 2 + 1] + g_u[ub + 1]) * inv + bc[1];
    out[ub + 0] = r0;
    out[ub + 1] = r1;
    int lab = (y_p[p] == y_g[h]) ? 1 : 0;
    if (mode == 1) {
        out[2 * MROWS + idx] = (float)lab;        // numeric float labels
    } else if (mode == 2) {
        long long* lp = reinterpret_cast<long long*>(out + 2 * MROWS);
        lp[idx] = (long long)lab;                 // int64 labels
    }
}

// ---------------------------------------------------------------------------
extern "C" void kernel_launch(void* const* d_in, const int* in_sizes, int n_in,
                              void* d_out, int out_size)
{
    const float* d   = (const float*)d_in[0];
    const int*   y_p = (const int*)d_in[1];
    const int*   y_g = (const int*)d_in[2];
    const float* W1  = (const float*)d_in[3];
    const float* b1  = (const float*)d_in[4];
    const float* g1  = (const float*)d_in[5];
    const float* be1 = (const float*)d_in[6];
    const float* rm1 = (const float*)d_in[7];
    const float* rv1 = (const float*)d_in[8];
    const float* W2  = (const float*)d_in[9];
    const float* b2  = (const float*)d_in[10];
    const float* g2  = (const float*)d_in[11];
    const float* be2 = (const float*)d_in[12];
    const float* rm2 = (const float*)d_in[13];
    const float* rv2 = (const float*)d_in[14];
    const float* Wc  = (const float*)d_in[15];
    const float* bc  = (const float*)d_in[16];
    float* out = (float*)d_out;

    // Output layout: 262144 floats of result, then (maybe) 131072 labels.
    int mode;
    if (out_size == 2 * MROWS) mode = 0;            // result only
    else if (out_size == 3 * MROWS) mode = 1;       // + float labels
    else mode = 2;                                  // + int64 labels

    zero_scratch_kernel<<<(MROWS * 2 + 255) / 256, 256>>>();

    dim3 grid(CDIM / 128, MROWS / 128);             // (4, 1024)
    gemm512_kernel<0><<<grid, 256>>>(d, W1, b1, g1, be1, rm1, rv1, nullptr);
    gemm512_kernel<1><<<grid, 256>>>(nullptr, W2, b2, g2, be2, rm2, rv2, Wc);

    class_sums_kernel<<<PDIM, 256>>>(y_g);
    finalize_kernel<<<(MROWS + 255) / 256, 256>>>(y_p, y_g, bc, out, mode);
}

// round 3
// speedup vs baseline: 3.3525x; 3.3525x over previous
#include <cuda_runtime.h>
#include <stdint.h>

// ---------------------------------------------------------------------------
// Problem constants
// ---------------------------------------------------------------------------
#define CDIM 512
#define GDIM 1024
#define PDIM 128
#define MROWS (PDIM * GDIM)      // 131072
#define NUM_IDS 64
#define EPS_BN 1e-5f

// ---------------------------------------------------------------------------
// Scratch (device globals; no cudaMalloc allowed)
// ---------------------------------------------------------------------------
__device__ float g_dr[(size_t)MROWS * CDIM];   // d pre-rounded to tf32
__device__ float g_h1[(size_t)MROWS * CDIM];   // h1 (tf32-rounded at store)
__device__ float g_WT1[CDIM * CDIM];           // W1^T, tf32-rounded, [N][K]
__device__ float g_WT2[CDIM * CDIM];           // W2^T, tf32-rounded
__device__ float g_u[MROWS * 2];               // u = t @ Wc (atomic partials)
__device__ float g_U[PDIM * NUM_IDS * 2];      // per-(p,class) sums
__device__ int   g_cnt[NUM_IDS];               // class counts of y_g

// ---------------------------------------------------------------------------
// Helpers
// ---------------------------------------------------------------------------
__device__ __forceinline__ uint32_t smem_u32(const void* p) {
    uint32_t a;
    asm("{ .reg .u64 t; cvta.to.shared.u64 t, %1; cvt.u32.u64 %0, t; }"
        : "=r"(a) : "l"(p));
    return a;
}
__device__ __forceinline__ float tf32_rna(float x) {
    uint32_t r;
    asm("cvt.rna.tf32.f32 %0, %1;" : "=r"(r) : "f"(x));
    return __uint_as_float(r);
}
__device__ __forceinline__ void cp16(uint32_t s, const void* g) {
    asm volatile("cp.async.cg.shared.global [%0], [%1], 16;" :: "r"(s), "l"(g) : "memory");
}
__device__ __forceinline__ void cp_commit() {
    asm volatile("cp.async.commit_group;" ::: "memory");
}
template <int N> __device__ __forceinline__ void cp_wait() {
    asm volatile("cp.async.wait_group %0;" :: "n"(N) : "memory");
}
// tf32 MMA: D[16,8] += A[16,8] * B[8,8] (A row-major, B col-major)
__device__ __forceinline__ void mma_tf32(float* c, const uint32_t* a, const uint32_t* b) {
    asm volatile(
        "mma.sync.aligned.m16n8k8.row.col.f32.tf32.tf32.f32 "
        "{%0,%1,%2,%3}, {%4,%5,%6,%7}, {%8,%9}, {%0,%1,%2,%3};"
        : "+f"(c[0]), "+f"(c[1]), "+f"(c[2]), "+f"(c[3])
        : "r"(a[0]), "r"(a[1]), "r"(a[2]), "r"(a[3]), "r"(b[0]), "r"(b[1]));
}

// ---------------------------------------------------------------------------
// GEMM config
// ---------------------------------------------------------------------------
#define BM 128
#define BN 128
#define BK 32
#define NCHUNK (CDIM / BK)       // 16
#define SKF 36                   // padded row stride in floats (144 B, 16B-aligned)
#define TILE_F (128 * SKF)       // 4608 floats per tile stage
// float-offsets in dynamic smem:
//   A stages: [0, 2*TILE_F) ; B stages: [2*TILE_F, 4*TILE_F)
//   coef: sc|of|wc0|wc1 (4*128) at 4*TILE_F ; sred (128*2) after
#define COEF_F  (4 * TILE_F)
#define SRED_F  (COEF_F + 512)
#define SMEM_TOTAL ((SRED_F + 256) * 4)   // 76800 bytes

// ---------------------------------------------------------------------------
// Small prep kernels
// ---------------------------------------------------------------------------
__global__ void zero_scratch_kernel() {
    int i = blockIdx.x * blockDim.x + threadIdx.x;
    if (i < MROWS * 2) g_u[i] = 0.0f;
    if (i < PDIM * NUM_IDS * 2) g_U[i] = 0.0f;
    if (i < NUM_IDS) g_cnt[i] = 0;
}

// Round d to tf32 (rna) once, so the GEMM mainloop needs no CVTs.
__global__ void round_d_kernel(const float* __restrict__ d) {
    size_t i = ((size_t)blockIdx.x * blockDim.x + threadIdx.x) * 4;
    float4 v = *reinterpret_cast<const float4*>(d + i);
    v.x = tf32_rna(v.x); v.y = tf32_rna(v.y);
    v.z = tf32_rna(v.z); v.w = tf32_rna(v.w);
    *reinterpret_cast<float4*>(g_dr + i) = v;
}

// W^T with tf32 rounding: g_WT[n][k] = tf32(W[k][n])
__global__ void transpose_w_kernel(const float* __restrict__ W1,
                                   const float* __restrict__ W2) {
    int n = blockIdx.x;
    for (int k = threadIdx.x; k < CDIM; k += blockDim.x) {
        g_WT1[n * CDIM + k] = tf32_rna(W1[k * CDIM + n]);
        g_WT2[n * CDIM + k] = tf32_rna(W2[k * CDIM + n]);
    }
}

// ---------------------------------------------------------------------------
// tf32 mma.sync GEMM: C = A[131072,512] @ W[512,512], fused epilogues.
// MODE 0: out = tf32(lrelu(bn1(.))) -> g_h1
// MODE 1: t = lrelu(bn2(.)); g_u[row] += t . Wc (2 cols)
// 256 threads = 8 warps: warp_m = wid&1 (64 rows), warp_n = wid>>1 (32 cols)
// ---------------------------------------------------------------------------
template <int MODE>
__global__ void __launch_bounds__(256)
gemm_mma_kernel(const float* __restrict__ bias,
                const float* __restrict__ gam,
                const float* __restrict__ bet,
                const float* __restrict__ rm,
                const float* __restrict__ rv,
                const float* __restrict__ Wc)
{
    extern __shared__ float sm[];
    const uint32_t sbase = smem_u32(sm);

    const float* __restrict__ Ag = (MODE == 0) ? g_dr : g_h1;
    const float* __restrict__ Bg = (MODE == 0) ? g_WT1 : g_WT2;

    const int tid = threadIdx.x;
    const int wid = tid >> 5;
    const int lane = tid & 31;
    const int l4 = lane & 3;
    const int lg = lane >> 2;            // 0..7
    const int bm = blockIdx.y * BM;
    const int bn = blockIdx.x * BN;
    const int warp_row = (wid & 1) * 64;
    const int warp_col = (wid >> 1) * 32;

    // coef + sred init
    float* sc_s  = sm + COEF_F;
    float* of_s  = sc_s + 128;
    float* wc0_s = sc_s + 256;
    float* wc1_s = sc_s + 384;
    float* sred  = sm + SRED_F;          // [128][2]
    if (tid < 128) {
        int col = bn + tid;
        float inv = rsqrtf(rv[col] + EPS_BN) * gam[col];
        sc_s[tid] = inv;
        of_s[tid] = (bias[col] - rm[col]) * inv + bet[col];
        if (MODE == 1) {
            wc0_s[tid] = Wc[col * 2 + 0];
            wc1_s[tid] = Wc[col * 2 + 1];
            sred[tid * 2 + 0] = 0.0f;
            sred[tid * 2 + 1] = 0.0f;
        }
    }

    float acc[4][4][4];
#pragma unroll
    for (int i = 0; i < 4; i++)
#pragma unroll
        for (int j = 0; j < 4; j++)
#pragma unroll
            for (int q = 0; q < 4; q++) acc[i][j][q] = 0.0f;

    // chunk loader: both tiles are 128 rows x 32 floats, padded stride 144B
    auto load_chunk = [&](int c) {
        const int s = c & 1;
        const float* aG = Ag + (size_t)bm * CDIM + c * BK;
        const uint32_t aB = sbase + s * (TILE_F * 4);
#pragma unroll
        for (int i = 0; i < 4; i++) {
            int idx = tid + i * 256;
            int row = idx >> 3, q = idx & 7;
            cp16(aB + row * 144 + q * 16, aG + (size_t)row * CDIM + q * 4);
        }
        const float* bG = Bg + (size_t)bn * CDIM + c * BK;
        const uint32_t bB = sbase + (2 + s) * (TILE_F * 4);
#pragma unroll
        for (int i = 0; i < 4; i++) {
            int idx = tid + i * 256;
            int row = idx >> 3, q = idx & 7;
            cp16(bB + row * 144 + q * 16, bG + (size_t)row * CDIM + q * 4);
        }
        cp_commit();
    };

    load_chunk(0);

    for (int c = 0; c < NCHUNK; c++) {
        const int s = c & 1;
        if (c + 1 < NCHUNK) { load_chunk(c + 1); cp_wait<1>(); }
        else                { cp_wait<0>(); }
        __syncthreads();

        const float* sA = sm + s * TILE_F;
        const float* sB = sm + (2 + s) * TILE_F;

#pragma unroll
        for (int ks = 0; ks < 4; ks++) {
            const int kk = ks * 8;
            uint32_t af[4][4];
#pragma unroll
            for (int mt = 0; mt < 4; mt++) {
                const float* p = sA + (warp_row + mt * 16 + lg) * SKF + kk + l4;
                af[mt][0] = __float_as_uint(p[0]);
                af[mt][1] = __float_as_uint(p[8 * SKF]);
                af[mt][2] = __float_as_uint(p[4]);
                af[mt][3] = __float_as_uint(p[8 * SKF + 4]);
            }
            uint32_t bf[4][2];
#pragma unroll
            for (int nt = 0; nt < 4; nt++) {
                const float* p = sB + (warp_col + nt * 8 + lg) * SKF + kk + l4;
                bf[nt][0] = __float_as_uint(p[0]);
                bf[nt][1] = __float_as_uint(p[4]);
            }
#pragma unroll
            for (int mt = 0; mt < 4; mt++)
#pragma unroll
                for (int nt = 0; nt < 4; nt++)
                    mma_tf32(acc[mt][nt], af[mt], bf[nt]);
        }
        __syncthreads();
    }

    // ------------------------- epilogue -------------------------
    if (MODE == 0) {
#pragma unroll
        for (int mt = 0; mt < 4; mt++) {
            const int r0 = bm + warp_row + mt * 16 + lg;
#pragma unroll
            for (int nt = 0; nt < 4; nt++) {
                const int cl = warp_col + nt * 8 + l4 * 2;
                const float s0 = sc_s[cl], s1 = sc_s[cl + 1];
                const float o0 = of_s[cl], o1 = of_s[cl + 1];
                float v;
                float2 w0, w1;
                v = fmaf(acc[mt][nt][0], s0, o0); v = v >= 0.f ? v : 0.1f * v; w0.x = tf32_rna(v);
                v = fmaf(acc[mt][nt][1], s1, o1); v = v >= 0.f ? v : 0.1f * v; w0.y = tf32_rna(v);
                v = fmaf(acc[mt][nt][2], s0, o0); v = v >= 0.f ? v : 0.1f * v; w1.x = tf32_rna(v);
                v = fmaf(acc[mt][nt][3], s1, o1); v = v >= 0.f ? v : 0.1f * v; w1.y = tf32_rna(v);
                *reinterpret_cast<float2*>(&g_h1[(size_t)r0 * CDIM + bn + cl]) = w0;
                *reinterpret_cast<float2*>(&g_h1[(size_t)(r0 + 8) * CDIM + bn + cl]) = w1;
            }
        }
    } else {
        float p[4][2][2];
#pragma unroll
        for (int mt = 0; mt < 4; mt++)
            for (int h = 0; h < 2; h++)
                for (int j = 0; j < 2; j++) p[mt][h][j] = 0.0f;
#pragma unroll
        for (int mt = 0; mt < 4; mt++) {
#pragma unroll
            for (int nt = 0; nt < 4; nt++) {
                const int cl = warp_col + nt * 8 + l4 * 2;
                const float s0 = sc_s[cl], s1 = sc_s[cl + 1];
                const float o0 = of_s[cl], o1 = of_s[cl + 1];
                const float a0 = wc0_s[cl], a1 = wc0_s[cl + 1];
                const float b0 = wc1_s[cl], b1 = wc1_s[cl + 1];
                float v00 = fmaf(acc[mt][nt][0], s0, o0); v00 = v00 >= 0.f ? v00 : 0.1f * v00;
                float v01 = fmaf(acc[mt][nt][1], s1, o1); v01 = v01 >= 0.f ? v01 : 0.1f * v01;
                float v10 = fmaf(acc[mt][nt][2], s0, o0); v10 = v10 >= 0.f ? v10 : 0.1f * v10;
                float v11 = fmaf(acc[mt][nt][3], s1, o1); v11 = v11 >= 0.f ? v11 : 0.1f * v11;
                p[mt][0][0] += v00 * a0 + v01 * a1;
                p[mt][0][1] += v00 * b0 + v01 * b1;
                p[mt][1][0] += v10 * a0 + v11 * a1;
                p[mt][1][1] += v10 * b0 + v11 * b1;
            }
        }
        // reduce across the 4 lanes sharing each row (lane xor 1, 2)
#pragma unroll
        for (int mt = 0; mt < 4; mt++)
#pragma unroll
            for (int h = 0; h < 2; h++)
#pragma unroll
                for (int j = 0; j < 2; j++) {
                    float v = p[mt][h][j];
                    v += __shfl_xor_sync(0xFFFFFFFFu, v, 1);
                    v += __shfl_xor_sync(0xFFFFFFFFu, v, 2);
                    p[mt][h][j] = v;
                }
        if (l4 == 0) {
#pragma unroll
            for (int mt = 0; mt < 4; mt++)
#pragma unroll
                for (int h = 0; h < 2; h++) {
                    int rl = warp_row + mt * 16 + lg + h * 8;
                    atomicAdd(&sred[rl * 2 + 0], p[mt][h][0]);
                    atomicAdd(&sred[rl * 2 + 1], p[mt][h][1]);
                }
        }
        __syncthreads();
        if (tid < 128) {
            atomicAdd(&g_u[(size_t)(bm + tid) * 2 + 0], sred[tid * 2 + 0]);
            atomicAdd(&g_u[(size_t)(bm + tid) * 2 + 1], sred[tid * 2 + 1]);
        }
    }
}

// ---------------------------------------------------------------------------
// Per-(p, class) sums of u; block per p. Block 0 records class counts.
// ---------------------------------------------------------------------------
__global__ void class_sums_kernel(const int* __restrict__ y_g) {
    int p = blockIdx.x;
    __shared__ float bins[NUM_IDS][2];
    __shared__ int cbin[NUM_IDS];
    int tid = threadIdx.x;
    if (tid < NUM_IDS) { bins[tid][0] = 0.0f; bins[tid][1] = 0.0f; cbin[tid] = 0; }
    __syncthreads();
    for (int g = tid; g < GDIM; g += blockDim.x) {
        int k = y_g[g];
        size_t base = (size_t)(p * GDIM + g) * 2;
        atomicAdd(&bins[k][0], g_u[base + 0]);
        atomicAdd(&bins[k][1], g_u[base + 1]);
        if (p == 0) atomicAdd(&cbin[k], 1);
    }
    __syncthreads();
    if (tid < NUM_IDS) {
        g_U[(p * NUM_IDS + tid) * 2 + 0] = bins[tid][0];
        g_U[(p * NUM_IDS + tid) * 2 + 1] = bins[tid][1];
        if (p == 0) g_cnt[tid] = cbin[tid];
    }
}

// ---------------------------------------------------------------------------
// Final assembly: result[p,h,:] = (U[p,class(h),:] + u[p,h,:])/(n_k+1) + bc
// ---------------------------------------------------------------------------
__global__ void finalize_kernel(const int* __restrict__ y_p,
                                const int* __restrict__ y_g,
                                const float* __restrict__ bc,
                                float* __restrict__ out, int mode)
{
    int idx = blockIdx.x * blockDim.x + threadIdx.x;
    if (idx >= MROWS) return;
    int p = idx >> 10;
    int h = idx & 1023;
    int k = y_g[h];
    float inv = 1.0f / (float)(g_cnt[k] + 1);
    size_t ub = (size_t)idx * 2;
    float r0 = (g_U[(p * NUM_IDS + k) * 2 + 0] + g_u[ub + 0]) * inv + bc[0];
    float r1 = (g_U[(p * NUM_IDS + k) * 2 + 1] + g_u[ub + 1]) * inv + bc[1];
    out[ub + 0] = r0;
    out[ub + 1] = r1;
    int lab = (y_p[p] == y_g[h]) ? 1 : 0;
    if (mode == 1) {
        out[2 * MROWS + idx] = (float)lab;
    } else if (mode == 2) {
        long long* lp = reinterpret_cast<long long*>(out + 2 * MROWS);
        lp[idx] = (long long)lab;
    }
}

// ---------------------------------------------------------------------------
extern "C" void kernel_launch(void* const* d_in, const int* in_sizes, int n_in,
                              void* d_out, int out_size)
{
    const float* d   = (const float*)d_in[0];
    const int*   y_p = (const int*)d_in[1];
    const int*   y_g = (const int*)d_in[2];
    const float* W1  = (const float*)d_in[3];
    const float* b1  = (const float*)d_in[4];
    const float* g1  = (const float*)d_in[5];
    const float* be1 = (const float*)d_in[6];
    const float* rm1 = (const float*)d_in[7];
    const float* rv1 = (const float*)d_in[8];
    const float* W2  = (const float*)d_in[9];
    const float* b2  = (const float*)d_in[10];
    const float* g2  = (const float*)d_in[11];
    const float* be2 = (const float*)d_in[12];
    const float* rm2 = (const float*)d_in[13];
    const float* rv2 = (const float*)d_in[14];
    const float* Wc  = (const float*)d_in[15];
    const float* bc  = (const float*)d_in[16];
    float* out = (float*)d_out;

    int mode;
    if (out_size == 2 * MROWS) mode = 0;
    else if (out_size == 3 * MROWS) mode = 1;
    else mode = 2;

    cudaFuncSetAttribute(gemm_mma_kernel<0>,
                         cudaFuncAttributeMaxDynamicSharedMemorySize, SMEM_TOTAL);
    cudaFuncSetAttribute(gemm_mma_kernel<1>,
                         cudaFuncAttributeMaxDynamicSharedMemorySize, SMEM_TOTAL);

    zero_scratch_kernel<<<(MROWS * 2 + 255) / 256, 256>>>();
    round_d_kernel<<<(MROWS * (CDIM / 4)) / 256, 256>>>(d);
    transpose_w_kernel<<<CDIM, 256>>>(W1, W2);

    dim3 grid(CDIM / BN, MROWS / BM);              // (4, 1024)
    gemm_mma_kernel<0><<<grid, 256, SMEM_TOTAL>>>(b1, g1, be1, rm1, rv1, nullptr);
    gemm_mma_kernel<1><<<grid, 256, SMEM_TOTAL>>>(b2, g2, be2, rm2, rv2, Wc);

    class_sums_kernel<<<PDIM, 256>>>(y_g);
    finalize_kernel<<<(MROWS + 255) / 256, 256>>>(y_p, y_g, bc, out, mode);
}

// round 5
// speedup vs baseline: 3.8999x; 1.1633x over previous
#include <cuda_runtime.h>
#include <stdint.h>

// ---------------------------------------------------------------------------
// Problem constants
// ---------------------------------------------------------------------------
#define CDIM 512
#define GDIM 1024
#define PDIM 128
#define MROWS (PDIM * GDIM)      // 131072
#define NUM_IDS 64
#define EPS_BN 1e-5f

// ---------------------------------------------------------------------------
// Scratch (device globals; no cudaMalloc allowed)
// ---------------------------------------------------------------------------
__device__ float g_h1[(size_t)MROWS * CDIM];   // h1 (tf32-rounded at store)
__device__ float g_WT1[CDIM * CDIM];           // W1^T, tf32-rounded, [N][K]
__device__ float g_WT2[CDIM * CDIM];           // W2^T, tf32-rounded
__device__ float g_u[MROWS * 2];               // u = t @ Wc (atomic partials)
__device__ float g_U[PDIM * NUM_IDS * 2];      // per-(p,class) sums
__device__ int   g_cnt[NUM_IDS];               // class counts of y_g

// ---------------------------------------------------------------------------
// Helpers
// ---------------------------------------------------------------------------
__device__ __forceinline__ uint32_t smem_u32(const void* p) {
    uint32_t a;
    asm("{ .reg .u64 t; cvta.to.shared.u64 t, %1; cvt.u32.u64 %0, t; }"
        : "=r"(a) : "l"(p));
    return a;
}
__device__ __forceinline__ float tf32_rna(float x) {
    uint32_t r;
    asm("cvt.rna.tf32.f32 %0, %1;" : "=r"(r) : "f"(x));
    return __uint_as_float(r);
}
__device__ __forceinline__ uint32_t tf32_rna_u(uint32_t x) {
    uint32_t r;
    asm("cvt.rna.tf32.f32 %0, %1;" : "=r"(r) : "f"(__uint_as_float(x)));
    return r;
}
__device__ __forceinline__ void cp16(uint32_t s, const void* g) {
    asm volatile("cp.async.cg.shared.global [%0], [%1], 16;" :: "r"(s), "l"(g) : "memory");
}
__device__ __forceinline__ void cp_commit() {
    asm volatile("cp.async.commit_group;" ::: "memory");
}
template <int N> __device__ __forceinline__ void cp_wait() {
    asm volatile("cp.async.wait_group %0;" :: "n"(N) : "memory");
}
// tf32 MMA: D[16,8] += A[16,8] * B[8,8] (A row-major, B col-major)
__device__ __forceinline__ void mma_tf32(float* c, const uint32_t* a, const uint32_t* b) {
    asm volatile(
        "mma.sync.aligned.m16n8k8.row.col.f32.tf32.tf32.f32 "
        "{%0,%1,%2,%3}, {%4,%5,%6,%7}, {%8,%9}, {%0,%1,%2,%3};"
        : "+f"(c[0]), "+f"(c[1]), "+f"(c[2]), "+f"(c[3])
        : "r"(a[0]), "r"(a[1]), "r"(a[2]), "r"(a[3]), "r"(b[0]), "r"(b[1]));
}

// ---------------------------------------------------------------------------
// GEMM config: CTA 128x128, 128 threads (4 warps, 2x2), warp tile 64x64
// ---------------------------------------------------------------------------
#define BM 128
#define BN 128
#define BK 32
#define NCHUNK (CDIM / BK)       // 16
#define SKF 36                   // padded row stride in floats (144 B)
#define TILE_F (128 * SKF)       // 4608 floats per tile stage
#define COEF_F  (4 * TILE_F)
#define SRED_F  (COEF_F + 512)
#define SMEM_TOTAL ((SRED_F + 256) * 4)   // 76800 bytes -> 2 CTAs/SM

// ---------------------------------------------------------------------------
// Small prep kernels
// ---------------------------------------------------------------------------
__global__ void zero_scratch_kernel() {
    int i = blockIdx.x * blockDim.x + threadIdx.x;
    if (i < MROWS * 2) g_u[i] = 0.0f;
    if (i < PDIM * NUM_IDS * 2) g_U[i] = 0.0f;
    if (i < NUM_IDS) g_cnt[i] = 0;
}

// W^T with tf32 rounding: g_WT[n][k] = tf32(W[k][n])
__global__ void transpose_w_kernel(const float* __restrict__ W1,
                                   const float* __restrict__ W2) {
    int n = blockIdx.x;
    for (int k = threadIdx.x; k < CDIM; k += blockDim.x) {
        g_WT1[n * CDIM + k] = tf32_rna(W1[k * CDIM + n]);
        g_WT2[n * CDIM + k] = tf32_rna(W2[k * CDIM + n]);
    }
}

// ---------------------------------------------------------------------------
// tf32 mma.sync GEMM: C = A[131072,512] @ W[512,512], fused epilogues.
// MODE 0: A = raw d param (rna applied to A-frags post-LDS); out -> g_h1
// MODE 1: A = g_h1 (device symbol, selected IN DEVICE CODE); epilogue t.Wc
// 128 threads = 4 warps: warp_m = wid&1 (64 rows), warp_n = wid>>1 (64 cols)
// ---------------------------------------------------------------------------
template <int MODE>
__global__ void __launch_bounds__(128, 2)
gemm_mma_kernel(const float* __restrict__ Ain,
                const float* __restrict__ bias,
                const float* __restrict__ gam,
                const float* __restrict__ bet,
                const float* __restrict__ rm,
                const float* __restrict__ rv,
                const float* __restrict__ Wc)
{
    extern __shared__ float sm[];
    const uint32_t sbase = smem_u32(sm);

    // IMPORTANT: device-symbol A selected here, NOT passed from host.
    const float* __restrict__ Ag = (MODE == 0) ? Ain : g_h1;
    const float* __restrict__ Bg = (MODE == 0) ? g_WT1 : g_WT2;

    const int tid = threadIdx.x;
    const int wid = tid >> 5;
    const int lane = tid & 31;
    const int l4 = lane & 3;
    const int lg = lane >> 2;            // 0..7
    const int bm = blockIdx.y * BM;
    const int bn = blockIdx.x * BN;
    const int warp_row = (wid & 1) * 64;
    const int warp_col = (wid >> 1) * 64;

    // coef + sred init
    float* sc_s  = sm + COEF_F;
    float* of_s  = sc_s + 128;
    float* wc0_s = sc_s + 256;
    float* wc1_s = sc_s + 384;
    float* sred  = sm + SRED_F;          // [128][2]
    {
        int col = bn + tid;
        float inv = rsqrtf(rv[col] + EPS_BN) * gam[col];
        sc_s[tid] = inv;
        of_s[tid] = (bias[col] - rm[col]) * inv + bet[col];
        if (MODE == 1) {
            wc0_s[tid] = Wc[col * 2 + 0];
            wc1_s[tid] = Wc[col * 2 + 1];
            sred[tid * 2 + 0] = 0.0f;
            sred[tid * 2 + 1] = 0.0f;
        }
    }

    float acc[4][8][4];
#pragma unroll
    for (int i = 0; i < 4; i++)
#pragma unroll
        for (int j = 0; j < 8; j++)
#pragma unroll
            for (int q = 0; q < 4; q++) acc[i][j][q] = 0.0f;

    // chunk loader: A and B tiles 128 rows x 32 floats, padded stride 144B
    auto load_chunk = [&](int c) {
        const int s = c & 1;
        const float* aG = Ag + (size_t)bm * CDIM + c * BK;
        const uint32_t aB = sbase + s * (TILE_F * 4);
#pragma unroll
        for (int i = 0; i < 8; i++) {
            int idx = tid + i * 128;
            int row = idx >> 3, q = idx & 7;
            cp16(aB + row * 144 + q * 16, aG + (size_t)row * CDIM + q * 4);
        }
        const float* bG = Bg + (size_t)bn * CDIM + c * BK;
        const uint32_t bB = sbase + (2 + s) * (TILE_F * 4);
#pragma unroll
        for (int i = 0; i < 8; i++) {
            int idx = tid + i * 128;
            int row = idx >> 3, q = idx & 7;
            cp16(bB + row * 144 + q * 16, bG + (size_t)row * CDIM + q * 4);
        }
        cp_commit();
    };

    // fragment loader for k-offset kk within stage s
    auto ldfrag = [&](int s, int kk, uint32_t af[4][4], uint32_t bf[8][2]) {
        const float* sA = sm + s * TILE_F;
        const float* sB = sm + (2 + s) * TILE_F;
#pragma unroll
        for (int mt = 0; mt < 4; mt++) {
            const float* p = sA + (warp_row + mt * 16 + lg) * SKF + kk + l4;
            af[mt][0] = __float_as_uint(p[0]);
            af[mt][1] = __float_as_uint(p[8 * SKF]);
            af[mt][2] = __float_as_uint(p[4]);
            af[mt][3] = __float_as_uint(p[8 * SKF + 4]);
            if (MODE == 0) {
                af[mt][0] = tf32_rna_u(af[mt][0]);
                af[mt][1] = tf32_rna_u(af[mt][1]);
                af[mt][2] = tf32_rna_u(af[mt][2]);
                af[mt][3] = tf32_rna_u(af[mt][3]);
            }
        }
#pragma unroll
        for (int nt = 0; nt < 8; nt++) {
            const float* p = sB + (warp_col + nt * 8 + lg) * SKF + kk + l4;
            bf[nt][0] = __float_as_uint(p[0]);
            bf[nt][1] = __float_as_uint(p[4]);
        }
    };

    auto mma_all = [&](uint32_t af[4][4], uint32_t bf[8][2]) {
#pragma unroll
        for (int mt = 0; mt < 4; mt++)
#pragma unroll
            for (int nt = 0; nt < 8; nt++)
                mma_tf32(acc[mt][nt], af[mt], bf[nt]);
    };

    uint32_t fA_a[4][4], fA_b[8][2];   // buffer A
    uint32_t fB_a[4][4], fB_b[8][2];   // buffer B

    load_chunk(0);
    cp_wait<0>();
    __syncthreads();
    ldfrag(0, 0, fA_a, fA_b);

    for (int c = 0; c < NCHUNK; c++) {
        const int s = c & 1;
        if (c + 1 < NCHUNK) load_chunk(c + 1);

        ldfrag(s, 8, fB_a, fB_b);
        mma_all(fA_a, fA_b);                 // ks0
        ldfrag(s, 16, fA_a, fA_b);
        mma_all(fB_a, fB_b);                 // ks1
        ldfrag(s, 24, fB_a, fB_b);
        mma_all(fA_a, fA_b);                 // ks2
        if (c + 1 < NCHUNK) {
            cp_wait<0>();
            __syncthreads();
            ldfrag(s ^ 1, 0, fA_a, fA_b);    // preload next chunk ks0
        }
        mma_all(fB_a, fB_b);                 // ks3
    }

    // ------------------------- epilogue -------------------------
    if (MODE == 0) {
#pragma unroll
        for (int mt = 0; mt < 4; mt++) {
            const int r0 = bm + warp_row + mt * 16 + lg;
#pragma unroll
            for (int nt = 0; nt < 8; nt++) {
                const int cl = warp_col + nt * 8 + l4 * 2;
                const float s0 = sc_s[cl], s1 = sc_s[cl + 1];
                const float o0 = of_s[cl], o1 = of_s[cl + 1];
                float v;
                float2 w0, w1;
                v = fmaf(acc[mt][nt][0], s0, o0); v = v >= 0.f ? v : 0.1f * v; w0.x = tf32_rna(v);
                v = fmaf(acc[mt][nt][1], s1, o1); v = v >= 0.f ? v : 0.1f * v; w0.y = tf32_rna(v);
                v = fmaf(acc[mt][nt][2], s0, o0); v = v >= 0.f ? v : 0.1f * v; w1.x = tf32_rna(v);
                v = fmaf(acc[mt][nt][3], s1, o1); v = v >= 0.f ? v : 0.1f * v; w1.y = tf32_rna(v);
                *reinterpret_cast<float2*>(&g_h1[(size_t)r0 * CDIM + bn + cl]) = w0;
                *reinterpret_cast<float2*>(&g_h1[(size_t)(r0 + 8) * CDIM + bn + cl]) = w1;
            }
        }
    } else {
        float p[4][2][2];
#pragma unroll
        for (int mt = 0; mt < 4; mt++)
            for (int h = 0; h < 2; h++)
                for (int j = 0; j < 2; j++) p[mt][h][j] = 0.0f;
#pragma unroll
        for (int mt = 0; mt < 4; mt++) {
#pragma unroll
            for (int nt = 0; nt < 8; nt++) {
                const int cl = warp_col + nt * 8 + l4 * 2;
                const float s0 = sc_s[cl], s1 = sc_s[cl + 1];
                const float o0 = of_s[cl], o1 = of_s[cl + 1];
                const float a0 = wc0_s[cl], a1 = wc0_s[cl + 1];
                const float b0 = wc1_s[cl], b1 = wc1_s[cl + 1];
                float v00 = fmaf(acc[mt][nt][0], s0, o0); v00 = v00 >= 0.f ? v00 : 0.1f * v00;
                float v01 = fmaf(acc[mt][nt][1], s1, o1); v01 = v01 >= 0.f ? v01 : 0.1f * v01;
                float v10 = fmaf(acc[mt][nt][2], s0, o0); v10 = v10 >= 0.f ? v10 : 0.1f * v10;
                float v11 = fmaf(acc[mt][nt][3], s1, o1); v11 = v11 >= 0.f ? v11 : 0.1f * v11;
                p[mt][0][0] += v00 * a0 + v01 * a1;
                p[mt][0][1] += v00 * b0 + v01 * b1;
                p[mt][1][0] += v10 * a0 + v11 * a1;
                p[mt][1][1] += v10 * b0 + v11 * b1;
            }
        }
        // reduce across the 4 lanes sharing each row
#pragma unroll
        for (int mt = 0; mt < 4; mt++)
#pragma unroll
            for (int h = 0; h < 2; h++)
#pragma unroll
                for (int j = 0; j < 2; j++) {
                    float v = p[mt][h][j];
                    v += __shfl_xor_sync(0xFFFFFFFFu, v, 1);
                    v += __shfl_xor_sync(0xFFFFFFFFu, v, 2);
                    p[mt][h][j] = v;
                }
        if (l4 == 0) {
#pragma unroll
            for (int mt = 0; mt < 4; mt++)
#pragma unroll
                for (int h = 0; h < 2; h++) {
                    int rl = warp_row + mt * 16 + lg + h * 8;
                    atomicAdd(&sred[rl * 2 + 0], p[mt][h][0]);
                    atomicAdd(&sred[rl * 2 + 1], p[mt][h][1]);
                }
        }
        __syncthreads();
        atomicAdd(&g_u[(size_t)(bm + tid) * 2 + 0], sred[tid * 2 + 0]);
        atomicAdd(&g_u[(size_t)(bm + tid) * 2 + 1], sred[tid * 2 + 1]);
    }
}

// ---------------------------------------------------------------------------
// Per-(p, class) sums of u; block per p. Block 0 records class counts.
// ---------------------------------------------------------------------------
__global__ void class_sums_kernel(const int* __restrict__ y_g) {
    int p = blockIdx.x;
    __shared__ float bins[NUM_IDS][2];
    __shared__ int cbin[NUM_IDS];
    int tid = threadIdx.x;
    if (tid < NUM_IDS) { bins[tid][0] = 0.0f; bins[tid][1] = 0.0f; cbin[tid] = 0; }
    __syncthreads();
    for (int g = tid; g < GDIM; g += blockDim.x) {
        int k = y_g[g];
        size_t base = (size_t)(p * GDIM + g) * 2;
        atomicAdd(&bins[k][0], g_u[base + 0]);
        atomicAdd(&bins[k][1], g_u[base + 1]);
        if (p == 0) atomicAdd(&cbin[k], 1);
    }
    __syncthreads();
    if (tid < NUM_IDS) {
        g_U[(p * NUM_IDS + tid) * 2 + 0] = bins[tid][0];
        g_U[(p * NUM_IDS + tid) * 2 + 1] = bins[tid][1];
        if (p == 0) g_cnt[tid] = cbin[tid];
    }
}

// ---------------------------------------------------------------------------
// Final assembly: result[p,h,:] = (U[p,class(h),:] + u[p,h,:])/(n_k+1) + bc
// ---------------------------------------------------------------------------
__global__ void finalize_kernel(const int* __restrict__ y_p,
                                const int* __restrict__ y_g,
                                const float* __restrict__ bc,
                                float* __restrict__ out, int mode)
{
    int idx = blockIdx.x * blockDim.x + threadIdx.x;
    if (idx >= MROWS) return;
    int p = idx >> 10;
    int h = idx & 1023;
    int k = y_g[h];
    float inv = 1.0f / (float)(g_cnt[k] + 1);
    size_t ub = (size_t)idx * 2;
    float r0 = (g_U[(p * NUM_IDS + k) * 2 + 0] + g_u[ub + 0]) * inv + bc[0];
    float r1 = (g_U[(p * NUM_IDS + k) * 2 + 1] + g_u[ub + 1]) * inv + bc[1];
    out[ub + 0] = r0;
    out[ub + 1] = r1;
    int lab = (y_p[p] == y_g[h]) ? 1 : 0;
    if (mode == 1) {
        out[2 * MROWS + idx] = (float)lab;
    } else if (mode == 2) {
        long long* lp = reinterpret_cast<long long*>(out + 2 * MROWS);
        lp[idx] = (long long)lab;
    }
}

// ---------------------------------------------------------------------------
extern "C" void kernel_launch(void* const* d_in, const int* in_sizes, int n_in,
                              void* d_out, int out_size)
{
    const float* d   = (const float*)d_in[0];
    const int*   y_p = (const int*)d_in[1];
    const int*   y_g = (const int*)d_in[2];
    const float* W1  = (const float*)d_in[3];
    const float* b1  = (const float*)d_in[4];
    const float* g1  = (const float*)d_in[5];
    const float* be1 = (const float*)d_in[6];
    const float* rm1 = (const float*)d_in[7];
    const float* rv1 = (const float*)d_in[8];
    const float* W2  = (const float*)d_in[9];
    const float* b2  = (const float*)d_in[10];
    const float* g2  = (const float*)d_in[11];
    const float* be2 = (const float*)d_in[12];
    const float* rm2 = (const float*)d_in[13];
    const float* rv2 = (const float*)d_in[14];
    const float* Wc  = (const float*)d_in[15];
    const float* bc  = (const float*)d_in[16];
    float* out = (float*)d_out;

    int mode;
    if (out_size == 2 * MROWS) mode = 0;
    else if (out_size == 3 * MROWS) mode = 1;
    else mode = 2;

    cudaFuncSetAttribute(gemm_mma_kernel<0>,
                         cudaFuncAttributeMaxDynamicSharedMemorySize, SMEM_TOTAL);
    cudaFuncSetAttribute(gemm_mma_kernel<1>,
                         cudaFuncAttributeMaxDynamicSharedMemorySize, SMEM_TOTAL);

    zero_scratch_kernel<<<(MROWS * 2 + 255) / 256, 256>>>();
    transpose_w_kernel<<<CDIM, 256>>>(W1, W2);

    dim3 grid(CDIM / BN, MROWS / BM);              // (4, 1024)
    gemm_mma_kernel<0><<<grid, 128, SMEM_TOTAL>>>(d, b1, g1, be1, rm1, rv1, nullptr);
    gemm_mma_kernel<1><<<grid, 128, SMEM_TOTAL>>>(d, b2, g2, be2, rm2, rv2, Wc);

    class_sums_kernel<<<PDIM, 256>>>(y_g);
    finalize_kernel<<<(MROWS + 255) / 256, 256>>>(y_p, y_g, bc, out, mode);
}

// round 6
// speedup vs baseline: 4.0703x; 1.0437x over previous
#include <cuda_runtime.h>
#include <stdint.h>

// ---------------------------------------------------------------------------
// Problem constants
// ---------------------------------------------------------------------------
#define CDIM 512
#define GDIM 1024
#define PDIM 128
#define MROWS (PDIM * GDIM)      // 131072
#define NUM_IDS 64
#define EPS_BN 1e-5f

// ---------------------------------------------------------------------------
// Scratch (device globals; no cudaMalloc allowed)
// ---------------------------------------------------------------------------
__device__ float g_h1[(size_t)MROWS * CDIM];   // h1 (tf32-rounded at store)
__device__ float g_WT1[CDIM * CDIM];           // W1^T, tf32-rounded, [N][K]
__device__ float g_WT2[CDIM * CDIM];           // W2^T, tf32-rounded
__device__ float g_u[MROWS * 2];               // u = t @ Wc (atomic partials)
__device__ float g_U[PDIM * NUM_IDS * 2];      // per-(p,class) sums
__device__ int   g_cnt[NUM_IDS];               // class counts of y_g

// ---------------------------------------------------------------------------
// Helpers
// ---------------------------------------------------------------------------
__device__ __forceinline__ uint32_t smem_u32(const void* p) {
    uint32_t a;
    asm("{ .reg .u64 t; cvta.to.shared.u64 t, %1; cvt.u32.u64 %0, t; }"
        : "=r"(a) : "l"(p));
    return a;
}
__device__ __forceinline__ float tf32_rna(float x) {
    uint32_t r;
    asm("cvt.rna.tf32.f32 %0, %1;" : "=r"(r) : "f"(x));
    return __uint_as_float(r);
}
__device__ __forceinline__ uint32_t tf32_rna_u(uint32_t x) {
    uint32_t r;
    asm("cvt.rna.tf32.f32 %0, %1;" : "=r"(r) : "f"(__uint_as_float(x)));
    return r;
}
__device__ __forceinline__ void cp16(uint32_t s, const void* g) {
    asm volatile("cp.async.cg.shared.global [%0], [%1], 16;" :: "r"(s), "l"(g) : "memory");
}
__device__ __forceinline__ void cp_commit() {
    asm volatile("cp.async.commit_group;" ::: "memory");
}
template <int N> __device__ __forceinline__ void cp_wait() {
    asm volatile("cp.async.wait_group %0;" :: "n"(N) : "memory");
}
// ldmatrix x4: 4 8x8 b16 matrices -> 4 regs; thread t of matrix i supplies
// row addresses for i = t/8; within a matrix thread t holds (t/4, t%4) as 4B.
__device__ __forceinline__ void ldsm4(uint32_t r[4], uint32_t addr) {
    asm volatile("ldmatrix.sync.aligned.m8n8.x4.shared.b16 {%0,%1,%2,%3}, [%4];"
                 : "=r"(r[0]), "=r"(r[1]), "=r"(r[2]), "=r"(r[3]) : "r"(addr));
}
// tf32 MMA: D[16,8] += A[16,8] * B[8,8] (A row-major, B col-major)
__device__ __forceinline__ void mma_tf32(float* c, const uint32_t* a, const uint32_t* b) {
    asm volatile(
        "mma.sync.aligned.m16n8k8.row.col.f32.tf32.tf32.f32 "
        "{%0,%1,%2,%3}, {%4,%5,%6,%7}, {%8,%9}, {%0,%1,%2,%3};"
        : "+f"(c[0]), "+f"(c[1]), "+f"(c[2]), "+f"(c[3])
        : "r"(a[0]), "r"(a[1]), "r"(a[2]), "r"(a[3]), "r"(b[0]), "r"(b[1]));
}

// ---------------------------------------------------------------------------
// GEMM config: CTA 128x128, 128 threads (4 warps, 2x2), warp tile 64x64
// ---------------------------------------------------------------------------
#define BM 128
#define BN 128
#define BK 32
#define NCHUNK (CDIM / BK)       // 16
#define SKF 36                   // padded row stride in floats (144 B)
#define TILE_F (128 * SKF)       // 4608 floats per tile stage
#define COEF_F  (4 * TILE_F)
#define SRED_F  (COEF_F + 512)
#define SMEM_TOTAL ((SRED_F + 256) * 4)   // 76800 bytes -> 2 CTAs/SM

// ---------------------------------------------------------------------------
// Small prep kernels
// ---------------------------------------------------------------------------
__global__ void zero_scratch_kernel() {
    int i = blockIdx.x * blockDim.x + threadIdx.x;
    if (i < MROWS * 2) g_u[i] = 0.0f;
    if (i < PDIM * NUM_IDS * 2) g_U[i] = 0.0f;
    if (i < NUM_IDS) g_cnt[i] = 0;
}

// W^T with tf32 rounding: g_WT[n][k] = tf32(W[k][n])
__global__ void transpose_w_kernel(const float* __restrict__ W1,
                                   const float* __restrict__ W2) {
    int n = blockIdx.x;
    for (int k = threadIdx.x; k < CDIM; k += blockDim.x) {
        g_WT1[n * CDIM + k] = tf32_rna(W1[k * CDIM + n]);
        g_WT2[n * CDIM + k] = tf32_rna(W2[k * CDIM + n]);
    }
}

// ---------------------------------------------------------------------------
// tf32 mma.sync GEMM: C = A[131072,512] @ W[512,512], fused epilogues.
// MODE 0: A = raw d param (rna applied to A-frags post-LDSM); out -> g_h1
// MODE 1: A = g_h1 (device symbol, selected IN DEVICE CODE); epilogue t.Wc
// 128 threads = 4 warps: warp_m = wid&1 (64 rows), warp_n = wid>>1 (64 cols)
// ---------------------------------------------------------------------------
template <int MODE>
__global__ void __launch_bounds__(128, 2)
gemm_mma_kernel(const float* __restrict__ Ain,
                const float* __restrict__ bias,
                const float* __restrict__ gam,
                const float* __restrict__ bet,
                const float* __restrict__ rm,
                const float* __restrict__ rv,
                const float* __restrict__ Wc)
{
    extern __shared__ float sm[];
    const uint32_t sbase = smem_u32(sm);

    // device-symbol A selected in device code (host can't pass symbol addr)
    const float* __restrict__ Ag = (MODE == 0) ? Ain : g_h1;
    const float* __restrict__ Bg = (MODE == 0) ? g_WT1 : g_WT2;

    const int tid = threadIdx.x;
    const int wid = tid >> 5;
    const int lane = tid & 31;
    const int l4 = lane & 3;
    const int lg = lane >> 2;            // 0..7
    const int bm = blockIdx.y * BM;
    const int bn = blockIdx.x * BN;
    const int warp_row = (wid & 1) * 64;
    const int warp_col = (wid >> 1) * 64;

    // ldmatrix per-thread source row/col-offset
    const int rlane = (lane < 16) ? lane : (lane - 16);
    const int kadd  = (lane < 16) ? 0 : 4;
    const uint32_t a_base = sbase + 4 * ((warp_row + rlane) * SKF + kadd);
    const uint32_t b_base = sbase + 4 * (2 * TILE_F + (warp_col + rlane) * SKF + kadd);

    // coef + sred init
    float* sc_s  = sm + COEF_F;
    float* of_s  = sc_s + 128;
    float* wc0_s = sc_s + 256;
    float* wc1_s = sc_s + 384;
    float* sred  = sm + SRED_F;          // [128][2]
    {
        int col = bn + tid;
        float inv = rsqrtf(rv[col] + EPS_BN) * gam[col];
        sc_s[tid] = inv;
        of_s[tid] = (bias[col] - rm[col]) * inv + bet[col];
        if (MODE == 1) {
            wc0_s[tid] = Wc[col * 2 + 0];
            wc1_s[tid] = Wc[col * 2 + 1];
            sred[tid * 2 + 0] = 0.0f;
            sred[tid * 2 + 1] = 0.0f;
        }
    }

    float acc[4][8][4];
#pragma unroll
    for (int i = 0; i < 4; i++)
#pragma unroll
        for (int j = 0; j < 8; j++)
#pragma unroll
            for (int q = 0; q < 4; q++) acc[i][j][q] = 0.0f;

    // chunk loader: A and B tiles 128 rows x 32 floats, padded stride 144B
    auto load_chunk = [&](int c) {
        const int s = c & 1;
        const float* aG = Ag + (size_t)bm * CDIM + c * BK;
        const uint32_t aB = sbase + s * (TILE_F * 4);
#pragma unroll
        for (int i = 0; i < 8; i++) {
            int idx = tid + i * 128;
            int row = idx >> 3, q = idx & 7;
            cp16(aB + row * 144 + q * 16, aG + (size_t)row * CDIM + q * 4);
        }
        const float* bG = Bg + (size_t)bn * CDIM + c * BK;
        const uint32_t bB = sbase + (2 + s) * (TILE_F * 4);
#pragma unroll
        for (int i = 0; i < 8; i++) {
            int idx = tid + i * 128;
            int row = idx >> 3, q = idx & 7;
            cp16(bB + row * 144 + q * 16, bG + (size_t)row * CDIM + q * 4);
        }
        cp_commit();
    };

    // fragment loader via ldmatrix: 4 LDSM for A (mt), 4 LDSM for B (nt pairs)
    auto ldfrag = [&](int s, int kk, uint32_t af[4][4], uint32_t bf[8][2]) {
        const uint32_t sa = a_base + 4 * (s * TILE_F + kk);
        const uint32_t sb = b_base + 4 * (s * TILE_F + kk);
#pragma unroll
        for (int mt = 0; mt < 4; mt++) {
            ldsm4(af[mt], sa + mt * (16 * SKF * 4));
            if (MODE == 0) {
                af[mt][0] = tf32_rna_u(af[mt][0]);
                af[mt][1] = tf32_rna_u(af[mt][1]);
                af[mt][2] = tf32_rna_u(af[mt][2]);
                af[mt][3] = tf32_rna_u(af[mt][3]);
            }
        }
#pragma unroll
        for (int ntp = 0; ntp < 4; ntp++) {
            uint32_t r[4];
            ldsm4(r, sb + ntp * (16 * SKF * 4));
            bf[2 * ntp + 0][0] = r[0];
            bf[2 * ntp + 1][0] = r[1];
            bf[2 * ntp + 0][1] = r[2];
            bf[2 * ntp + 1][1] = r[3];
        }
    };

    auto mma_all = [&](uint32_t af[4][4], uint32_t bf[8][2]) {
#pragma unroll
        for (int mt = 0; mt < 4; mt++)
#pragma unroll
            for (int nt = 0; nt < 8; nt++)
                mma_tf32(acc[mt][nt], af[mt], bf[nt]);
    };

    uint32_t fA_a[4][4], fA_b[8][2];   // frag buffer A
    uint32_t fB_a[4][4], fB_b[8][2];   // frag buffer B

    load_chunk(0);
    cp_wait<0>();
    __syncthreads();
    ldfrag(0, 0, fA_a, fA_b);

    for (int c = 0; c < NCHUNK; c++) {
        const int s = c & 1;
        if (c + 1 < NCHUNK) load_chunk(c + 1);

        ldfrag(s, 8, fB_a, fB_b);
        mma_all(fA_a, fA_b);                 // ks0
        ldfrag(s, 16, fA_a, fA_b);
        mma_all(fB_a, fB_b);                 // ks1
        ldfrag(s, 24, fB_a, fB_b);
        mma_all(fA_a, fA_b);                 // ks2
        if (c + 1 < NCHUNK) {
            cp_wait<0>();
            __syncthreads();
            ldfrag(s ^ 1, 0, fA_a, fA_b);    // preload next chunk ks0
        }
        mma_all(fB_a, fB_b);                 // ks3
    }

    // ------------------------- epilogue -------------------------
    if (MODE == 0) {
#pragma unroll
        for (int mt = 0; mt < 4; mt++) {
            const int r0 = bm + warp_row + mt * 16 + lg;
#pragma unroll
            for (int nt = 0; nt < 8; nt++) {
                const int cl = warp_col + nt * 8 + l4 * 2;
                const float s0 = sc_s[cl], s1 = sc_s[cl + 1];
                const float o0 = of_s[cl], o1 = of_s[cl + 1];
                float v;
                float2 w0, w1;
                v = fmaf(acc[mt][nt][0], s0, o0); v = v >= 0.f ? v : 0.1f * v; w0.x = tf32_rna(v);
                v = fmaf(acc[mt][nt][1], s1, o1); v = v >= 0.f ? v : 0.1f * v; w0.y = tf32_rna(v);
                v = fmaf(acc[mt][nt][2], s0, o0); v = v >= 0.f ? v : 0.1f * v; w1.x = tf32_rna(v);
                v = fmaf(acc[mt][nt][3], s1, o1); v = v >= 0.f ? v : 0.1f * v; w1.y = tf32_rna(v);
                *reinterpret_cast<float2*>(&g_h1[(size_t)r0 * CDIM + bn + cl]) = w0;
                *reinterpret_cast<float2*>(&g_h1[(size_t)(r0 + 8) * CDIM + bn + cl]) = w1;
            }
        }
    } else {
        float p[4][2][2];
#pragma unroll
        for (int mt = 0; mt < 4; mt++)
            for (int h = 0; h < 2; h++)
                for (int j = 0; j < 2; j++) p[mt][h][j] = 0.0f;
#pragma unroll
        for (int mt = 0; mt < 4; mt++) {
#pragma unroll
            for (int nt = 0; nt < 8; nt++) {
                const int cl = warp_col + nt * 8 + l4 * 2;
                const float s0 = sc_s[cl], s1 = sc_s[cl + 1];
                const float o0 = of_s[cl], o1 = of_s[cl + 1];
                const float a0 = wc0_s[cl], a1 = wc0_s[cl + 1];
                const float b0 = wc1_s[cl], b1 = wc1_s[cl + 1];
                float v00 = fmaf(acc[mt][nt][0], s0, o0); v00 = v00 >= 0.f ? v00 : 0.1f * v00;
                float v01 = fmaf(acc[mt][nt][1], s1, o1); v01 = v01 >= 0.f ? v01 : 0.1f * v01;
                float v10 = fmaf(acc[mt][nt][2], s0, o0); v10 = v10 >= 0.f ? v10 : 0.1f * v10;
                float v11 = fmaf(acc[mt][nt][3], s1, o1); v11 = v11 >= 0.f ? v11 : 0.1f * v11;
                p[mt][0][0] += v00 * a0 + v01 * a1;
                p[mt][0][1] += v00 * b0 + v01 * b1;
                p[mt][1][0] += v10 * a0 + v11 * a1;
                p[mt][1][1] += v10 * b0 + v11 * b1;
            }
        }
        // reduce across the 4 lanes sharing each row
#pragma unroll
        for (int mt = 0; mt < 4; mt++)
#pragma unroll
            for (int h = 0; h < 2; h++)
#pragma unroll
                for (int j = 0; j < 2; j++) {
                    float v = p[mt][h][j];
                    v += __shfl_xor_sync(0xFFFFFFFFu, v, 1);
                    v += __shfl_xor_sync(0xFFFFFFFFu, v, 2);
                    p[mt][h][j] = v;
                }
        if (l4 == 0) {
#pragma unroll
            for (int mt = 0; mt < 4; mt++)
#pragma unroll
                for (int h = 0; h < 2; h++) {
                    int rl = warp_row + mt * 16 + lg + h * 8;
                    atomicAdd(&sred[rl * 2 + 0], p[mt][h][0]);
                    atomicAdd(&sred[rl * 2 + 1], p[mt][h][1]);
                }
        }
        __syncthreads();
        atomicAdd(&g_u[(size_t)(bm + tid) * 2 + 0], sred[tid * 2 + 0]);
        atomicAdd(&g_u[(size_t)(bm + tid) * 2 + 1], sred[tid * 2 + 1]);
    }
}

// ---------------------------------------------------------------------------
// Per-(p, class) sums of u; block per p. Block 0 records class counts.
// ---------------------------------------------------------------------------
__global__ void class_sums_kernel(const int* __restrict__ y_g) {
    int p = blockIdx.x;
    __shared__ float bins[NUM_IDS][2];
    __shared__ int cbin[NUM_IDS];
    int tid = threadIdx.x;
    if (tid < NUM_IDS) { bins[tid][0] = 0.0f; bins[tid][1] = 0.0f; cbin[tid] = 0; }
    __syncthreads();
    for (int g = tid; g < GDIM; g += blockDim.x) {
        int k = y_g[g];
        size_t base = (size_t)(p * GDIM + g) * 2;
        atomicAdd(&bins[k][0], g_u[base + 0]);
        atomicAdd(&bins[k][1], g_u[base + 1]);
        if (p == 0) atomicAdd(&cbin[k], 1);
    }
    __syncthreads();
    if (tid < NUM_IDS) {
        g_U[(p * NUM_IDS + tid) * 2 + 0] = bins[tid][0];
        g_U[(p * NUM_IDS + tid) * 2 + 1] = bins[tid][1];
        if (p == 0) g_cnt[tid] = cbin[tid];
    }
}

// ---------------------------------------------------------------------------
// Final assembly: result[p,h,:] = (U[p,class(h),:] + u[p,h,:])/(n_k+1) + bc
// ---------------------------------------------------------------------------
__global__ void finalize_kernel(const int* __restrict__ y_p,
                                const int* __restrict__ y_g,
                                const float* __restrict__ bc,
                                float* __restrict__ out, int mode)
{
    int idx = blockIdx.x * blockDim.x + threadIdx.x;
    if (idx >= MROWS) return;
    int p = idx >> 10;
    int h = idx & 1023;
    int k = y_g[h];
    float inv = 1.0f / (float)(g_cnt[k] + 1);
    size_t ub = (size_t)idx * 2;
    float r0 = (g_U[(p * NUM_IDS + k) * 2 + 0] + g_u[ub + 0]) * inv + bc[0];
    float r1 = (g_U[(p * NUM_IDS + k) * 2 + 1] + g_u[ub + 1]) * inv + bc[1];
    out[ub + 0] = r0;
    out[ub + 1] = r1;
    int lab = (y_p[p] == y_g[h]) ? 1 : 0;
    if (mode == 1) {
        out[2 * MROWS + idx] = (float)lab;
    } else if (mode == 2) {
        long long* lp = reinterpret_cast<long long*>(out + 2 * MROWS);
        lp[idx] = (long long)lab;
    }
}

// ---------------------------------------------------------------------------
extern "C" void kernel_launch(void* const* d_in, const int* in_sizes, int n_in,
                              void* d_out, int out_size)
{
    const float* d   = (const float*)d_in[0];
    const int*   y_p = (const int*)d_in[1];
    const int*   y_g = (const int*)d_in[2];
    const float* W1  = (const float*)d_in[3];
    const float* b1  = (const float*)d_in[4];
    const float* g1  = (const float*)d_in[5];
    const float* be1 = (const float*)d_in[6];
    const float* rm1 = (const float*)d_in[7];
    const float* rv1 = (const float*)d_in[8];
    const float* W2  = (const float*)d_in[9];
    const float* b2  = (const float*)d_in[10];
    const float* g2  = (const float*)d_in[11];
    const float* be2 = (const float*)d_in[12];
    const float* rm2 = (const float*)d_in[13];
    const float* rv2 = (const float*)d_in[14];
    const float* Wc  = (const float*)d_in[15];
    const float* bc  = (const float*)d_in[16];
    float* out = (float*)d_out;

    int mode;
    if (out_size == 2 * MROWS) mode = 0;
    else if (out_size == 3 * MROWS) mode = 1;
    else mode = 2;

    cudaFuncSetAttribute(gemm_mma_kernel<0>,
                         cudaFuncAttributeMaxDynamicSharedMemorySize, SMEM_TOTAL);
    cudaFuncSetAttribute(gemm_mma_kernel<1>,
                         cudaFuncAttributeMaxDynamicSharedMemorySize, SMEM_TOTAL);

    zero_scratch_kernel<<<(MROWS * 2 + 255) / 256, 256>>>();
    transpose_w_kernel<<<CDIM, 256>>>(W1, W2);

    dim3 grid(CDIM / BN, MROWS / BM);              // (4, 1024)
    gemm_mma_kernel<0><<<grid, 128, SMEM_TOTAL>>>(d, b1, g1, be1, rm1, rv1, nullptr);
    gemm_mma_kernel<1><<<grid, 128, SMEM_TOTAL>>>(d, b2, g2, be2, rm2, rv2, Wc);

    class_sums_kernel<<<PDIM, 256>>>(y_g);
    finalize_kernel<<<(MROWS + 255) / 256, 256>>>(y_p, y_g, bc, out, mode);
}

// round 7
// speedup vs baseline: 4.6183x; 1.1346x over previous
#include <cuda_runtime.h>
#include <stdint.h>

// ---------------------------------------------------------------------------
// Problem constants
// ---------------------------------------------------------------------------
#define CDIM 512
#define GDIM 1024
#define PDIM 128
#define MROWS (PDIM * GDIM)      // 131072
#define NUM_IDS 64
#define EPS_BN 1e-5f

// ---------------------------------------------------------------------------
// Scratch (device globals; no cudaMalloc allowed)
// ---------------------------------------------------------------------------
__device__ float g_h1[(size_t)MROWS * CDIM];   // h1 (tf32-rounded at store)
__device__ float g_WT1[CDIM * CDIM];           // W1^T, tf32-rounded, [N][K]
__device__ float g_WT2[CDIM * CDIM];           // W2^T, tf32-rounded
__device__ float g_u[MROWS * 2];               // u = t @ Wc (atomic partials)
__device__ float g_U[PDIM * NUM_IDS * 2];      // per-(p,class) sums
__device__ int   g_cnt[NUM_IDS];               // class counts of y_g

// ---------------------------------------------------------------------------
// Helpers
// ---------------------------------------------------------------------------
__device__ __forceinline__ uint32_t smem_u32(const void* p) {
    uint32_t a;
    asm("{ .reg .u64 t; cvta.to.shared.u64 t, %1; cvt.u32.u64 %0, t; }"
        : "=r"(a) : "l"(p));
    return a;
}
__device__ __forceinline__ float tf32_rna(float x) {
    uint32_t r;
    asm("cvt.rna.tf32.f32 %0, %1;" : "=r"(r) : "f"(x));
    return __uint_as_float(r);
}
__device__ __forceinline__ uint32_t tf32_rna_u(uint32_t x) {
    uint32_t r;
    asm("cvt.rna.tf32.f32 %0, %1;" : "=r"(r) : "f"(__uint_as_float(x)));
    return r;
}
__device__ __forceinline__ void cp16(uint32_t s, const void* g) {
    asm volatile("cp.async.cg.shared.global [%0], [%1], 16;" :: "r"(s), "l"(g) : "memory");
}
__device__ __forceinline__ void cp_commit() {
    asm volatile("cp.async.commit_group;" ::: "memory");
}
template <int N> __device__ __forceinline__ void cp_wait() {
    asm volatile("cp.async.wait_group %0;" :: "n"(N) : "memory");
}
// ldmatrix x4: 4 8x8 b16 matrices -> 4 regs
__device__ __forceinline__ void ldsm4(uint32_t r[4], uint32_t addr) {
    asm volatile("ldmatrix.sync.aligned.m8n8.x4.shared.b16 {%0,%1,%2,%3}, [%4];"
                 : "=r"(r[0]), "=r"(r[1]), "=r"(r[2]), "=r"(r[3]) : "r"(addr));
}
// tf32 MMA: D[16,8] += A[16,8] * B[8,8] (A row-major, B col-major)
__device__ __forceinline__ void mma_tf32(float* c, const uint32_t* a, const uint32_t* b) {
    asm volatile(
        "mma.sync.aligned.m16n8k8.row.col.f32.tf32.tf32.f32 "
        "{%0,%1,%2,%3}, {%4,%5,%6,%7}, {%8,%9}, {%0,%1,%2,%3};"
        : "+f"(c[0]), "+f"(c[1]), "+f"(c[2]), "+f"(c[3])
        : "r"(a[0]), "r"(a[1]), "r"(a[2]), "r"(a[3]), "r"(b[0]), "r"(b[1]));
}

// ---------------------------------------------------------------------------
// GEMM config: CTA 128x128, 128 threads (4 warps, 2x2), warp tile 64x64
// 3-stage cp.async pipeline, XOR-swizzled smem (rows of 128B, SW128 pattern)
// ---------------------------------------------------------------------------
#define BM 128
#define BN 128
#define BK 32
#define NCHUNK (CDIM / BK)       // 16
#define NSTAGE 3
#define ATILE 16384              // 128 rows * 128 B
#define BOFF  (NSTAGE * ATILE)   // 49152
#define COEF_B (2 * NSTAGE * ATILE)  // 98304 (byte offset)
#define COEF_F (COEF_B / 4)          // 24576 (float offset)
#define SRED_F (COEF_F + 512)
#define SMEM_TOTAL ((SRED_F + 256) * 4)  // 101376 bytes -> 2 CTAs/SM

// ---------------------------------------------------------------------------
// Small prep kernels
// ---------------------------------------------------------------------------
__global__ void zero_scratch_kernel() {
    int i = blockIdx.x * blockDim.x + threadIdx.x;
    if (i < MROWS * 2) g_u[i] = 0.0f;
    if (i < PDIM * NUM_IDS * 2) g_U[i] = 0.0f;
    if (i < NUM_IDS) g_cnt[i] = 0;
}

// W^T with tf32 rounding: g_WT[n][k] = tf32(W[k][n])
__global__ void transpose_w_kernel(const float* __restrict__ W1,
                                   const float* __restrict__ W2) {
    int n = blockIdx.x;
    for (int k = threadIdx.x; k < CDIM; k += blockDim.x) {
        g_WT1[n * CDIM + k] = tf32_rna(W1[k * CDIM + n]);
        g_WT2[n * CDIM + k] = tf32_rna(W2[k * CDIM + n]);
    }
}

// ---------------------------------------------------------------------------
// tf32 mma.sync GEMM: C = A[131072,512] @ W[512,512], fused epilogues.
// MODE 0: A = raw d param (rna applied to A-frags post-LDSM); out -> g_h1
// MODE 1: A = g_h1 (device symbol, selected IN DEVICE CODE); epilogue t.Wc
// ---------------------------------------------------------------------------
template <int MODE>
__global__ void __launch_bounds__(128, 2)
gemm_mma_kernel(const float* __restrict__ Ain,
                const float* __restrict__ bias,
                const float* __restrict__ gam,
                const float* __restrict__ bet,
                const float* __restrict__ rm,
                const float* __restrict__ rv,
                const float* __restrict__ Wc)
{
    extern __shared__ float sm[];
    const uint32_t sbase = smem_u32(sm);

    const float* __restrict__ Ag = (MODE == 0) ? Ain : g_h1;
    const float* __restrict__ Bg = (MODE == 0) ? g_WT1 : g_WT2;

    const int tid = threadIdx.x;
    const int wid = tid >> 5;
    const int lane = tid & 31;
    const int l4 = lane & 3;
    const int lg = lane >> 2;            // 0..7
    const int bm = blockIdx.y * BM;
    const int bn = blockIdx.x * BN;
    const int warp_row = (wid & 1) * 64;
    const int warp_col = (wid >> 1) * 64;

    // ldmatrix addressing: per-thread row + constant XOR mask (SW128 swizzle)
    const int rlane = (lane < 16) ? lane : (lane - 16);
    const int kadd4 = (lane < 16) ? 0 : 16;        // byte offset of k-halves
    const uint32_t xmask = (uint32_t)((rlane & 7) << 4);
    const uint32_t a_row_base = sbase + (uint32_t)(warp_row + rlane) * 128;
    const uint32_t b_row_base = sbase + BOFF + (uint32_t)(warp_col + rlane) * 128;

    // coef + sred init
    float* sc_s  = sm + COEF_F;
    float* of_s  = sc_s + 128;
    float* wc0_s = sc_s + 256;
    float* wc1_s = sc_s + 384;
    float* sred  = sm + SRED_F;          // [128][2]
    {
        int col = bn + tid;
        float inv = rsqrtf(rv[col] + EPS_BN) * gam[col];
        sc_s[tid] = inv;
        of_s[tid] = (bias[col] - rm[col]) * inv + bet[col];
        if (MODE == 1) {
            wc0_s[tid] = Wc[col * 2 + 0];
            wc1_s[tid] = Wc[col * 2 + 1];
            sred[tid * 2 + 0] = 0.0f;
            sred[tid * 2 + 1] = 0.0f;
        }
    }

    float acc[4][8][4];
#pragma unroll
    for (int i = 0; i < 4; i++)
#pragma unroll
        for (int j = 0; j < 8; j++)
#pragma unroll
            for (int q = 0; q < 4; q++) acc[i][j][q] = 0.0f;

    // chunk loader -> stage (c % 3), swizzled rows of 128 B
    auto load_chunk = [&](int c) {
        const int s = c % NSTAGE;
        const float* aG = Ag + (size_t)bm * CDIM + c * BK;
        const uint32_t aB = sbase + s * ATILE;
#pragma unroll
        for (int i = 0; i < 8; i++) {
            int idx = tid + i * 128;
            int row = idx >> 3, q = idx & 7;
            uint32_t sw = (uint32_t)(q * 16) ^ (uint32_t)((row & 7) << 4);
            cp16(aB + row * 128 + sw, aG + (size_t)row * CDIM + q * 4);
        }
        const float* bG = Bg + (size_t)bn * CDIM + c * BK;
        const uint32_t bB = sbase + BOFF + s * ATILE;
#pragma unroll
        for (int i = 0; i < 8; i++) {
            int idx = tid + i * 128;
            int row = idx >> 3, q = idx & 7;
            uint32_t sw = (uint32_t)(q * 16) ^ (uint32_t)((row & 7) << 4);
            cp16(bB + row * 128 + sw, bG + (size_t)row * CDIM + q * 4);
        }
        cp_commit();
    };

    // fragment loader via ldmatrix (stage s, k-offset kk in floats)
    auto ldfrag = [&](int s, int kk, uint32_t af[4][4], uint32_t bf[8][2]) {
        const uint32_t col = ((uint32_t)(kk * 4 + kadd4)) ^ xmask;
        const uint32_t sa = a_row_base + s * ATILE + col;
        const uint32_t sb = b_row_base + s * ATILE + col;
#pragma unroll
        for (int mt = 0; mt < 4; mt++) {
            ldsm4(af[mt], sa + mt * (16 * 128));
            if (MODE == 0) {
                af[mt][0] = tf32_rna_u(af[mt][0]);
                af[mt][1] = tf32_rna_u(af[mt][1]);
                af[mt][2] = tf32_rna_u(af[mt][2]);
                af[mt][3] = tf32_rna_u(af[mt][3]);
            }
        }
#pragma unroll
        for (int ntp = 0; ntp < 4; ntp++) {
            uint32_t r[4];
            ldsm4(r, sb + ntp * (16 * 128));
            bf[2 * ntp + 0][0] = r[0];
            bf[2 * ntp + 1][0] = r[1];
            bf[2 * ntp + 0][1] = r[2];
            bf[2 * ntp + 1][1] = r[3];
        }
    };

    auto mma_all = [&](uint32_t af[4][4], uint32_t bf[8][2]) {
#pragma unroll
        for (int mt = 0; mt < 4; mt++)
#pragma unroll
            for (int nt = 0; nt < 8; nt++)
                mma_tf32(acc[mt][nt], af[mt], bf[nt]);
    };

    uint32_t fA_a[4][4], fA_b[8][2];   // frag buffer A
    uint32_t fB_a[4][4], fB_b[8][2];   // frag buffer B

    // Prologue: fill 2 stages, arm frags for chunk 0
    load_chunk(0);
    load_chunk(1);
    cp_wait<1>();          // chunk 0 complete (chunk 1 may be in flight)
    __syncthreads();
    ldfrag(0, 0, fA_a, fA_b);

    for (int c = 0; c < NCHUNK; c++) {
        const int s = c % NSTAGE;
        if (c + 2 < NCHUNK) load_chunk(c + 2);   // fill stage (c+2)%3

        ldfrag(s, 8, fB_a, fB_b);
        mma_all(fA_a, fA_b);                 // ks0
        ldfrag(s, 16, fA_a, fA_b);
        mma_all(fB_a, fB_b);                 // ks1
        ldfrag(s, 24, fB_a, fB_b);
        mma_all(fA_a, fA_b);                 // ks2
        if (c + 1 < NCHUNK) {
            if (c + 2 < NCHUNK) cp_wait<1>();   // chunk c+1 done, c+2 in flight
            else                cp_wait<0>();   // tail: nothing else pending
            __syncthreads();
            ldfrag((c + 1) % NSTAGE, 0, fA_a, fA_b);  // preload next chunk ks0
        }
        mma_all(fB_a, fB_b);                 // ks3
    }

    // ------------------------- epilogue -------------------------
    if (MODE == 0) {
#pragma unroll
        for (int mt = 0; mt < 4; mt++) {
            const int r0 = bm + warp_row + mt * 16 + lg;
#pragma unroll
            for (int nt = 0; nt < 8; nt++) {
                const int cl = warp_col + nt * 8 + l4 * 2;
                const float s0 = sc_s[cl], s1 = sc_s[cl + 1];
                const float o0 = of_s[cl], o1 = of_s[cl + 1];
                float v;
                float2 w0, w1;
                v = fmaf(acc[mt][nt][0], s0, o0); v = v >= 0.f ? v : 0.1f * v; w0.x = tf32_rna(v);
                v = fmaf(acc[mt][nt][1], s1, o1); v = v >= 0.f ? v : 0.1f * v; w0.y = tf32_rna(v);
                v = fmaf(acc[mt][nt][2], s0, o0); v = v >= 0.f ? v : 0.1f * v; w1.x = tf32_rna(v);
                v = fmaf(acc[mt][nt][3], s1, o1); v = v >= 0.f ? v : 0.1f * v; w1.y = tf32_rna(v);
                *reinterpret_cast<float2*>(&g_h1[(size_t)r0 * CDIM + bn + cl]) = w0;
                *reinterpret_cast<float2*>(&g_h1[(size_t)(r0 + 8) * CDIM + bn + cl]) = w1;
            }
        }
    } else {
        float p[4][2][2];
#pragma unroll
        for (int mt = 0; mt < 4; mt++)
            for (int h = 0; h < 2; h++)
                for (int j = 0; j < 2; j++) p[mt][h][j] = 0.0f;
#pragma unroll
        for (int mt = 0; mt < 4; mt++) {
#pragma unroll
            for (int nt = 0; nt < 8; nt++) {
                const int cl = warp_col + nt * 8 + l4 * 2;
                const float s0 = sc_s[cl], s1 = sc_s[cl + 1];
                const float o0 = of_s[cl], o1 = of_s[cl + 1];
                const float a0 = wc0_s[cl], a1 = wc0_s[cl + 1];
                const float b0 = wc1_s[cl], b1 = wc1_s[cl + 1];
                float v00 = fmaf(acc[mt][nt][0], s0, o0); v00 = v00 >= 0.f ? v00 : 0.1f * v00;
                float v01 = fmaf(acc[mt][nt][1], s1, o1); v01 = v01 >= 0.f ? v01 : 0.1f * v01;
                float v10 = fmaf(acc[mt][nt][2], s0, o0); v10 = v10 >= 0.f ? v10 : 0.1f * v10;
                float v11 = fmaf(acc[mt][nt][3], s1, o1); v11 = v11 >= 0.f ? v11 : 0.1f * v11;
                p[mt][0][0] += v00 * a0 + v01 * a1;
                p[mt][0][1] += v00 * b0 + v01 * b1;
                p[mt][1][0] += v10 * a0 + v11 * a1;
                p[mt][1][1] += v10 * b0 + v11 * b1;
            }
        }
        // reduce across the 4 lanes sharing each row
#pragma unroll
        for (int mt = 0; mt < 4; mt++)
#pragma unroll
            for (int h = 0; h < 2; h++)
#pragma unroll
                for (int j = 0; j < 2; j++) {
                    float v = p[mt][h][j];
                    v += __shfl_xor_sync(0xFFFFFFFFu, v, 1);
                    v += __shfl_xor_sync(0xFFFFFFFFu, v, 2);
                    p[mt][h][j] = v;
                }
        if (l4 == 0) {
#pragma unroll
            for (int mt = 0; mt < 4; mt++)
#pragma unroll
                for (int h = 0; h < 2; h++) {
                    int rl = warp_row + mt * 16 + lg + h * 8;
                    atomicAdd(&sred[rl * 2 + 0], p[mt][h][0]);
                    atomicAdd(&sred[rl * 2 + 1], p[mt][h][1]);
                }
        }
        __syncthreads();
        atomicAdd(&g_u[(size_t)(bm + tid) * 2 + 0], sred[tid * 2 + 0]);
        atomicAdd(&g_u[(size_t)(bm + tid) * 2 + 1], sred[tid * 2 + 1]);
    }
}

// ---------------------------------------------------------------------------
// Per-(p, class) sums of u; block per p. Block 0 records class counts.
// ---------------------------------------------------------------------------
__global__ void class_sums_kernel(const int* __restrict__ y_g) {
    int p = blockIdx.x;
    __shared__ float bins[NUM_IDS][2];
    __shared__ int cbin[NUM_IDS];
    int tid = threadIdx.x;
    if (tid < NUM_IDS) { bins[tid][0] = 0.0f; bins[tid][1] = 0.0f; cbin[tid] = 0; }
    __syncthreads();
    for (int g = tid; g < GDIM; g += blockDim.x) {
        int k = y_g[g];
        size_t base = (size_t)(p * GDIM + g) * 2;
        atomicAdd(&bins[k][0], g_u[base + 0]);
        atomicAdd(&bins[k][1], g_u[base + 1]);
        if (p == 0) atomicAdd(&cbin[k], 1);
    }
    __syncthreads();
    if (tid < NUM_IDS) {
        g_U[(p * NUM_IDS + tid) * 2 + 0] = bins[tid][0];
        g_U[(p * NUM_IDS + tid) * 2 + 1] = bins[tid][1];
        if (p == 0) g_cnt[tid] = cbin[tid];
    }
}

// ---------------------------------------------------------------------------
// Final assembly: result[p,h,:] = (U[p,class(h),:] + u[p,h,:])/(n_k+1) + bc
// ---------------------------------------------------------------------------
__global__ void finalize_kernel(const int* __restrict__ y_p,
                                const int* __restrict__ y_g,
                                const float* __restrict__ bc,
                                float* __restrict__ out, int mode)
{
    int idx = blockIdx.x * blockDim.x + threadIdx.x;
    if (idx >= MROWS) return;
    int p = idx >> 10;
    int h = idx & 1023;
    int k = y_g[h];
    float inv = 1.0f / (float)(g_cnt[k] + 1);
    size_t ub = (size_t)idx * 2;
    float r0 = (g_U[(p * NUM_IDS + k) * 2 + 0] + g_u[ub + 0]) * inv + bc[0];
    float r1 = (g_U[(p * NUM_IDS + k) * 2 + 1] + g_u[ub + 1]) * inv + bc[1];
    out[ub + 0] = r0;
    out[ub + 1] = r1;
    int lab = (y_p[p] == y_g[h]) ? 1 : 0;
    if (mode == 1) {
        out[2 * MROWS + idx] = (float)lab;
    } else if (mode == 2) {
        long long* lp = reinterpret_cast<long long*>(out + 2 * MROWS);
        lp[idx] = (long long)lab;
    }
}

// ---------------------------------------------------------------------------
extern "C" void kernel_launch(void* const* d_in, const int* in_sizes, int n_in,
                              void* d_out, int out_size)
{
    const float* d   = (const float*)d_in[0];
    const int*   y_p = (const int*)d_in[1];
    const int*   y_g = (const int*)d_in[2];
    const float* W1  = (const float*)d_in[3];
    const float* b1  = (const float*)d_in[4];
    const float* g1  = (const float*)d_in[5];
    const float* be1 = (const float*)d_in[6];
    const float* rm1 = (const float*)d_in[7];
    const float* rv1 = (const float*)d_in[8];
    const float* W2  = (const float*)d_in[9];
    const float* b2  = (const float*)d_in[10];
    const float* g2  = (const float*)d_in[11];
    const float* be2 = (const float*)d_in[12];
    const float* rm2 = (const float*)d_in[13];
    const float* rv2 = (const float*)d_in[14];
    const float* Wc  = (const float*)d_in[15];
    const float* bc  = (const float*)d_in[16];
    float* out = (float*)d_out;

    int mode;
    if (out_size == 2 * MROWS) mode = 0;
    else if (out_size == 3 * MROWS) mode = 1;
    else mode = 2;

    cudaFuncSetAttribute(gemm_mma_kernel<0>,
                         cudaFuncAttributeMaxDynamicSharedMemorySize, SMEM_TOTAL);
    cudaFuncSetAttribute(gemm_mma_kernel<1>,
                         cudaFuncAttributeMaxDynamicSharedMemorySize, SMEM_TOTAL);

    zero_scratch_kernel<<<(MROWS * 2 + 255) / 256, 256>>>();
    transpose_w_kernel<<<CDIM, 256>>>(W1, W2);

    dim3 grid(CDIM / BN, MROWS / BM);              // (4, 1024)
    gemm_mma_kernel<0><<<grid, 128, SMEM_TOTAL>>>(d, b1, g1, be1, rm1, rv1, nullptr);
    gemm_mma_kernel<1><<<grid, 128, SMEM_TOTAL>>>(d, b2, g2, be2, rm2, rv2, Wc);

    class_sums_kernel<<<PDIM, 256>>>(y_g);
    finalize_kernel<<<(MROWS + 255) / 256, 256>>>(y_p, y_g, bc, out, mode);
}

// round 8
// speedup vs baseline: 7.3712x; 1.5961x over previous
#include <cuda_runtime.h>
#include <cuda_fp16.h>
#include <stdint.h>

// ---------------------------------------------------------------------------
// Problem constants
// ---------------------------------------------------------------------------
#define CDIM 512
#define GDIM 1024
#define PDIM 128
#define MROWS (PDIM * GDIM)      // 131072
#define NUM_IDS 64
#define EPS_BN 1e-5f

// ---------------------------------------------------------------------------
// Scratch (device globals; no cudaMalloc allowed)
// ---------------------------------------------------------------------------
__device__ __half g_dh[(size_t)MROWS * CDIM];  // d converted to fp16 (128 MB)
__device__ __half g_h1[(size_t)MROWS * CDIM];  // h1 in fp16 (128 MB)
__device__ __half g_WTh1[CDIM * CDIM];         // W1^T fp16, [N][K]
__device__ __half g_WTh2[CDIM * CDIM];         // W2^T fp16
__device__ float  g_u[MROWS * 2];              // u = t @ Wc (atomic partials)
__device__ float  g_U[PDIM * NUM_IDS * 2];     // per-(p,class) sums
__device__ int    g_cnt[NUM_IDS];              // class counts of y_g

// ---------------------------------------------------------------------------
// Helpers
// ---------------------------------------------------------------------------
__device__ __forceinline__ uint32_t smem_u32(const void* p) {
    uint32_t a;
    asm("{ .reg .u64 t; cvta.to.shared.u64 t, %1; cvt.u32.u64 %0, t; }"
        : "=r"(a) : "l"(p));
    return a;
}
__device__ __forceinline__ void cp16(uint32_t s, const void* g) {
    asm volatile("cp.async.cg.shared.global [%0], [%1], 16;" :: "r"(s), "l"(g) : "memory");
}
__device__ __forceinline__ void cp_commit() {
    asm volatile("cp.async.commit_group;" ::: "memory");
}
template <int N> __device__ __forceinline__ void cp_wait() {
    asm volatile("cp.async.wait_group %0;" :: "n"(N) : "memory");
}
// ldmatrix x4: 4 8x8 b16 matrices -> 4 regs
__device__ __forceinline__ void ldsm4(uint32_t r[4], uint32_t addr) {
    asm volatile("ldmatrix.sync.aligned.m8n8.x4.shared.b16 {%0,%1,%2,%3}, [%4];"
                 : "=r"(r[0]), "=r"(r[1]), "=r"(r[2]), "=r"(r[3]) : "r"(addr));
}
// fp16 MMA k16: D[16,8] += A[16,16] * B[16,8], fp32 accumulate
__device__ __forceinline__ void mma_f16(float* c, const uint32_t* a, const uint32_t* b) {
    asm volatile(
        "mma.sync.aligned.m16n8k16.row.col.f32.f16.f16.f32 "
        "{%0,%1,%2,%3}, {%4,%5,%6,%7}, {%8,%9}, {%0,%1,%2,%3};"
        : "+f"(c[0]), "+f"(c[1]), "+f"(c[2]), "+f"(c[3])
        : "r"(a[0]), "r"(a[1]), "r"(a[2]), "r"(a[3]), "r"(b[0]), "r"(b[1]));
}

// ---------------------------------------------------------------------------
// GEMM config: CTA 128x128, 128 threads (4 warps, 2x2), warp tile 64x64
// fp16 operands, BK=64 (128-B rows), 3-stage cp.async ring, SW128 swizzle
// ---------------------------------------------------------------------------
#define BM 128
#define BN 128
#define BK 64
#define NCHUNK (CDIM / BK)       // 8
#define NSTAGE 3
#define ATILE 16384              // 128 rows * 128 B
#define BOFF  (NSTAGE * ATILE)   // 49152
#define COEF_B (2 * NSTAGE * ATILE)  // 98304 bytes
#define COEF_F (COEF_B / 4)
#define SRED_F (COEF_F + 512)
#define SMEM_TOTAL ((SRED_F + 256) * 4)  // 101376 bytes -> 2 CTAs/SM

// ---------------------------------------------------------------------------
// Small prep kernels
// ---------------------------------------------------------------------------
__global__ void zero_scratch_kernel() {
    int i = blockIdx.x * blockDim.x + threadIdx.x;
    if (i < MROWS * 2) g_u[i] = 0.0f;
    if (i < PDIM * NUM_IDS * 2) g_U[i] = 0.0f;
    if (i < NUM_IDS) g_cnt[i] = 0;
}

// d (fp32) -> g_dh (fp16), 8 elements per thread
__global__ void cvt_d_kernel(const float* __restrict__ d) {
    size_t i = ((size_t)blockIdx.x * blockDim.x + threadIdx.x) * 8;
    float4 v0 = *reinterpret_cast<const float4*>(d + i);
    float4 v1 = *reinterpret_cast<const float4*>(d + i + 4);
    __half2 h[4];
    h[0] = __floats2half2_rn(v0.x, v0.y);
    h[1] = __floats2half2_rn(v0.z, v0.w);
    h[2] = __floats2half2_rn(v1.x, v1.y);
    h[3] = __floats2half2_rn(v1.z, v1.w);
    *reinterpret_cast<uint4*>(g_dh + i) = *reinterpret_cast<uint4*>(h);
}

// W^T in fp16: g_WTh[n][k] = fp16(W[k][n])
__global__ void transpose_w_kernel(const float* __restrict__ W1,
                                   const float* __restrict__ W2) {
    int n = blockIdx.x;
    for (int k = threadIdx.x; k < CDIM; k += blockDim.x) {
        g_WTh1[n * CDIM + k] = __float2half_rn(W1[k * CDIM + n]);
        g_WTh2[n * CDIM + k] = __float2half_rn(W2[k * CDIM + n]);
    }
}

// ---------------------------------------------------------------------------
// fp16 mma.sync GEMM: C = A[131072,512] @ W[512,512], fused epilogues.
// MODE 0: A = g_dh; out = fp16(lrelu(bn1(.))) -> g_h1
// MODE 1: A = g_h1; t = lrelu(bn2(.)); g_u[row] += t . Wc
// ---------------------------------------------------------------------------
template <int MODE>
__global__ void __launch_bounds__(128, 2)
gemm_mma_kernel(const float* __restrict__ bias,
                const float* __restrict__ gam,
                const float* __restrict__ bet,
                const float* __restrict__ rm,
                const float* __restrict__ rv,
                const float* __restrict__ Wc)
{
    extern __shared__ float sm[];
    const uint32_t sbase = smem_u32(sm);

    const __half* __restrict__ Ag = (MODE == 0) ? g_dh : g_h1;
    const __half* __restrict__ Bg = (MODE == 0) ? g_WTh1 : g_WTh2;

    const int tid = threadIdx.x;
    const int wid = tid >> 5;
    const int lane = tid & 31;
    const int l4 = lane & 3;
    const int lg = lane >> 2;            // 0..7
    const int bm = blockIdx.y * BM;
    const int bn = blockIdx.x * BN;
    const int warp_row = (wid & 1) * 64;
    const int warp_col = (wid >> 1) * 64;

    // ldmatrix addressing: per-thread row + constant XOR mask (SW128 swizzle)
    const int rlane = (lane < 16) ? lane : (lane - 16);
    const int kadd  = (lane < 16) ? 0 : 16;        // byte offset of k-halves (8 fp16)
    const uint32_t xmask = (uint32_t)((rlane & 7) << 4);
    const uint32_t a_row_base = sbase + (uint32_t)(warp_row + rlane) * 128;
    const uint32_t b_row_base = sbase + BOFF + (uint32_t)(warp_col + rlane) * 128;

    // coef + sred init
    float* sc_s  = sm + COEF_F;
    float* of_s  = sc_s + 128;
    float* wc0_s = sc_s + 256;
    float* wc1_s = sc_s + 384;
    float* sred  = sm + SRED_F;          // [128][2]
    {
        int col = bn + tid;
        float inv = rsqrtf(rv[col] + EPS_BN) * gam[col];
        sc_s[tid] = inv;
        of_s[tid] = (bias[col] - rm[col]) * inv + bet[col];
        if (MODE == 1) {
            wc0_s[tid] = Wc[col * 2 + 0];
            wc1_s[tid] = Wc[col * 2 + 1];
            sred[tid * 2 + 0] = 0.0f;
            sred[tid * 2 + 1] = 0.0f;
        }
    }

    float acc[4][8][4];
#pragma unroll
    for (int i = 0; i < 4; i++)
#pragma unroll
        for (int j = 0; j < 8; j++)
#pragma unroll
            for (int q = 0; q < 4; q++) acc[i][j][q] = 0.0f;

    // chunk loader -> stage (c % 3); tiles 128 rows x 64 fp16 (128 B), swizzled
    auto load_chunk = [&](int c) {
        const int s = c % NSTAGE;
        const __half* aG = Ag + (size_t)bm * CDIM + c * BK;
        const uint32_t aB = sbase + s * ATILE;
#pragma unroll
        for (int i = 0; i < 8; i++) {
            int idx = tid + i * 128;
            int row = idx >> 3, q = idx & 7;
            uint32_t sw = (uint32_t)(q * 16) ^ (uint32_t)((row & 7) << 4);
            cp16(aB + row * 128 + sw, aG + (size_t)row * CDIM + q * 8);
        }
        const __half* bG = Bg + (size_t)bn * CDIM + c * BK;
        const uint32_t bB = sbase + BOFF + s * ATILE;
#pragma unroll
        for (int i = 0; i < 8; i++) {
            int idx = tid + i * 128;
            int row = idx >> 3, q = idx & 7;
            uint32_t sw = (uint32_t)(q * 16) ^ (uint32_t)((row & 7) << 4);
            cp16(bB + row * 128 + sw, bG + (size_t)row * CDIM + q * 8);
        }
        cp_commit();
    };

    // fragment loader via ldmatrix (stage s, k-byte offset kb in {0,32,64,96})
    auto ldfrag = [&](int s, int kb, uint32_t af[4][4], uint32_t bf[8][2]) {
        const uint32_t col = ((uint32_t)(kb + kadd)) ^ xmask;
        const uint32_t sa = a_row_base + s * ATILE + col;
        const uint32_t sb = b_row_base + s * ATILE + col;
#pragma unroll
        for (int mt = 0; mt < 4; mt++)
            ldsm4(af[mt], sa + mt * (16 * 128));
#pragma unroll
        for (int ntp = 0; ntp < 4; ntp++) {
            uint32_t r[4];
            ldsm4(r, sb + ntp * (16 * 128));
            bf[2 * ntp + 0][0] = r[0];
            bf[2 * ntp + 1][0] = r[1];
            bf[2 * ntp + 0][1] = r[2];
            bf[2 * ntp + 1][1] = r[3];
        }
    };

    auto mma_all = [&](uint32_t af[4][4], uint32_t bf[8][2]) {
#pragma unroll
        for (int mt = 0; mt < 4; mt++)
#pragma unroll
            for (int nt = 0; nt < 8; nt++)
                mma_f16(acc[mt][nt], af[mt], bf[nt]);
    };

    uint32_t fA_a[4][4], fA_b[8][2];   // frag buffer A
    uint32_t fB_a[4][4], fB_b[8][2];   // frag buffer B

    // Prologue: fill 2 stages, arm frags for chunk 0
    load_chunk(0);
    load_chunk(1);
    cp_wait<1>();          // chunk 0 complete (chunk 1 may be in flight)
    __syncthreads();
    ldfrag(0, 0, fA_a, fA_b);

    for (int c = 0; c < NCHUNK; c++) {
        const int s = c % NSTAGE;
        if (c + 2 < NCHUNK) load_chunk(c + 2);   // fill stage (c+2)%3

        ldfrag(s, 32, fB_a, fB_b);
        mma_all(fA_a, fA_b);                 // k 0-15
        ldfrag(s, 64, fA_a, fA_b);
        mma_all(fB_a, fB_b);                 // k 16-31
        ldfrag(s, 96, fB_a, fB_b);
        mma_all(fA_a, fA_b);                 // k 32-47
        if (c + 1 < NCHUNK) {
            if (c + 2 < NCHUNK) cp_wait<1>();   // chunk c+1 done, c+2 in flight
            else                cp_wait<0>();
            __syncthreads();
            ldfrag((c + 1) % NSTAGE, 0, fA_a, fA_b);  // preload next chunk
        }
        mma_all(fB_a, fB_b);                 // k 48-63
    }

    // ------------------------- epilogue -------------------------
    if (MODE == 0) {
#pragma unroll
        for (int mt = 0; mt < 4; mt++) {
            const int r0 = bm + warp_row + mt * 16 + lg;
#pragma unroll
            for (int nt = 0; nt < 8; nt++) {
                const int cl = warp_col + nt * 8 + l4 * 2;
                const float s0 = sc_s[cl], s1 = sc_s[cl + 1];
                const float o0 = of_s[cl], o1 = of_s[cl + 1];
                float v0, v1;
                v0 = fmaf(acc[mt][nt][0], s0, o0); v0 = v0 >= 0.f ? v0 : 0.1f * v0;
                v1 = fmaf(acc[mt][nt][1], s1, o1); v1 = v1 >= 0.f ? v1 : 0.1f * v1;
                *reinterpret_cast<__half2*>(&g_h1[(size_t)r0 * CDIM + bn + cl]) =
                    __floats2half2_rn(v0, v1);
                v0 = fmaf(acc[mt][nt][2], s0, o0); v0 = v0 >= 0.f ? v0 : 0.1f * v0;
                v1 = fmaf(acc[mt][nt][3], s1, o1); v1 = v1 >= 0.f ? v1 : 0.1f * v1;
                *reinterpret_cast<__half2*>(&g_h1[(size_t)(r0 + 8) * CDIM + bn + cl]) =
                    __floats2half2_rn(v0, v1);
            }
        }
    } else {
        float p[4][2][2];
#pragma unroll
        for (int mt = 0; mt < 4; mt++)
            for (int h = 0; h < 2; h++)
                for (int j = 0; j < 2; j++) p[mt][h][j] = 0.0f;
#pragma unroll
        for (int mt = 0; mt < 4; mt++) {
#pragma unroll
            for (int nt = 0; nt < 8; nt++) {
                const int cl = warp_col + nt * 8 + l4 * 2;
                const float s0 = sc_s[cl], s1 = sc_s[cl + 1];
                const float o0 = of_s[cl], o1 = of_s[cl + 1];
                const float a0 = wc0_s[cl], a1 = wc0_s[cl + 1];
                const float b0 = wc1_s[cl], b1 = wc1_s[cl + 1];
                float v00 = fmaf(acc[mt][nt][0], s0, o0); v00 = v00 >= 0.f ? v00 : 0.1f * v00;
                float v01 = fmaf(acc[mt][nt][1], s1, o1); v01 = v01 >= 0.f ? v01 : 0.1f * v01;
                float v10 = fmaf(acc[mt][nt][2], s0, o0); v10 = v10 >= 0.f ? v10 : 0.1f * v10;
                float v11 = fmaf(acc[mt][nt][3], s1, o1); v11 = v11 >= 0.f ? v11 : 0.1f * v11;
                p[mt][0][0] += v00 * a0 + v01 * a1;
                p[mt][0][1] += v00 * b0 + v01 * b1;
                p[mt][1][0] += v10 * a0 + v11 * a1;
                p[mt][1][1] += v10 * b0 + v11 * b1;
            }
        }
        // reduce across the 4 lanes sharing each row
#pragma unroll
        for (int mt = 0; mt < 4; mt++)
#pragma unroll
            for (int h = 0; h < 2; h++)
#pragma unroll
                for (int j = 0; j < 2; j++) {
                    float v = p[mt][h][j];
                    v += __shfl_xor_sync(0xFFFFFFFFu, v, 1);
                    v += __shfl_xor_sync(0xFFFFFFFFu, v, 2);
                    p[mt][h][j] = v;
                }
        if (l4 == 0) {
#pragma unroll
            for (int mt = 0; mt < 4; mt++)
#pragma unroll
                for (int h = 0; h < 2; h++) {
                    int rl = warp_row + mt * 16 + lg + h * 8;
                    atomicAdd(&sred[rl * 2 + 0], p[mt][h][0]);
                    atomicAdd(&sred[rl * 2 + 1], p[mt][h][1]);
                }
        }
        __syncthreads();
        atomicAdd(&g_u[(size_t)(bm + tid) * 2 + 0], sred[tid * 2 + 0]);
        atomicAdd(&g_u[(size_t)(bm + tid) * 2 + 1], sred[tid * 2 + 1]);
    }
}

// ---------------------------------------------------------------------------
// Per-(p, class) sums of u; block per p. Block 0 records class counts.
// ---------------------------------------------------------------------------
__global__ void class_sums_kernel(const int* __restrict__ y_g) {
    int p = blockIdx.x;
    __shared__ float bins[NUM_IDS][2];
    __shared__ int cbin[NUM_IDS];
    int tid = threadIdx.x;
    if (tid < NUM_IDS) { bins[tid][0] = 0.0f; bins[tid][1] = 0.0f; cbin[tid] = 0; }
    __syncthreads();
    for (int g = tid; g < GDIM; g += blockDim.x) {
        int k = y_g[g];
        size_t base = (size_t)(p * GDIM + g) * 2;
        atomicAdd(&bins[k][0], g_u[base + 0]);
        atomicAdd(&bins[k][1], g_u[base + 1]);
        if (p == 0) atomicAdd(&cbin[k], 1);
    }
    __syncthreads();
    if (tid < NUM_IDS) {
        g_U[(p * NUM_IDS + tid) * 2 + 0] = bins[tid][0];
        g_U[(p * NUM_IDS + tid) * 2 + 1] = bins[tid][1];
        if (p == 0) g_cnt[tid] = cbin[tid];
    }
}

// ---------------------------------------------------------------------------
// Final assembly: result[p,h,:] = (U[p,class(h),:] + u[p,h,:])/(n_k+1) + bc
// ---------------------------------------------------------------------------
__global__ void finalize_kernel(const int* __restrict__ y_p,
                                const int* __restrict__ y_g,
                                const float* __restrict__ bc,
                                float* __restrict__ out, int mode)
{
    int idx = blockIdx.x * blockDim.x + threadIdx.x;
    if (idx >= MROWS) return;
    int p = idx >> 10;
    int h = idx & 1023;
    int k = y_g[h];
    float inv = 1.0f / (float)(g_cnt[k] + 1);
    size_t ub = (size_t)idx * 2;
    float r0 = (g_U[(p * NUM_IDS + k) * 2 + 0] + g_u[ub + 0]) * inv + bc[0];
    float r1 = (g_U[(p * NUM_IDS + k) * 2 + 1] + g_u[ub + 1]) * inv + bc[1];
    out[ub + 0] = r0;
    out[ub + 1] = r1;
    int lab = (y_p[p] == y_g[h]) ? 1 : 0;
    if (mode == 1) {
        out[2 * MROWS + idx] = (float)lab;
    } else if (mode == 2) {
        long long* lp = reinterpret_cast<long long*>(out + 2 * MROWS);
        lp[idx] = (long long)lab;
    }
}

// ---------------------------------------------------------------------------
extern "C" void kernel_launch(void* const* d_in, const int* in_sizes, int n_in,
                              void* d_out, int out_size)
{
    const float* d   = (const float*)d_in[0];
    const int*   y_p = (const int*)d_in[1];
    const int*   y_g = (const int*)d_in[2];
    const float* W1  = (const float*)d_in[3];
    const float* b1  = (const float*)d_in[4];
    const float* g1  = (const float*)d_in[5];
    const float* be1 = (const float*)d_in[6];
    const float* rm1 = (const float*)d_in[7];
    const float* rv1 = (const float*)d_in[8];
    const float* W2  = (const float*)d_in[9];
    const float* b2  = (const float*)d_in[10];
    const float* g2  = (const float*)d_in[11];
    const float* be2 = (const float*)d_in[12];
    const float* rm2 = (const float*)d_in[13];
    const float* rv2 = (const float*)d_in[14];
    const float* Wc  = (const float*)d_in[15];
    const float* bc  = (const float*)d_in[16];
    float* out = (float*)d_out;

    int mode;
    if (out_size == 2 * MROWS) mode = 0;
    else if (out_size == 3 * MROWS) mode = 1;
    else mode = 2;

    cudaFuncSetAttribute(gemm_mma_kernel<0>,
                         cudaFuncAttributeMaxDynamicSharedMemorySize, SMEM_TOTAL);
    cudaFuncSetAttribute(gemm_mma_kernel<1>,
                         cudaFuncAttributeMaxDynamicSharedMemorySize, SMEM_TOTAL);

    zero_scratch_kernel<<<(MROWS * 2 + 255) / 256, 256>>>();
    cvt_d_kernel<<<((size_t)MROWS * CDIM / 8) / 256, 256>>>(d);
    transpose_w_kernel<<<CDIM, 256>>>(W1, W2);

    dim3 grid(CDIM / BN, MROWS / BM);              // (4, 1024)
    gemm_mma_kernel<0><<<grid, 128, SMEM_TOTAL>>>(b1, g1, be1, rm1, rv1, nullptr);
    gemm_mma_kernel<1><<<grid, 128, SMEM_TOTAL>>>(b2, g2, be2, rm2, rv2, Wc);

    class_sums_kernel<<<PDIM, 256>>>(y_g);
    finalize_kernel<<<(MROWS + 255) / 256, 256>>>(y_p, y_g, bc, out, mode);
}